// round 2
// baseline (speedup 1.0000x reference)
#include <cuda_runtime.h>
#include <math.h>

#define BB  2
#define PP  64
#define NBB 64
#define TT  256
#define VV  32
#define HH  4
#define AO  32
#define LAT 64
#define RS  68
#define ROWS 33

__device__ float g_att_main[BB*PP*AO];
__device__ float g_att_self[BB*PP*VV*AO];
__device__ float g_bterm[BB*NBB*LAT];

__device__ __forceinline__ float tanh_fast(float x) {
    float e = __expf(2.0f * x);
    return 1.0f - __fdividef(2.0f, e + 1.0f);
}

// ---------------- prep: boundary term of MLP layer-1 + zero output ----------
__global__ void prep_kernel(const float* __restrict__ bcoords,
                            const float* __restrict__ W1,
                            float* __restrict__ out) {
    int bn = blockIdx.x, d = threadIdx.x;
    const float* bc = bcoords + bn * 4;
    g_bterm[bn*LAT + d] = bc[0]*W1[4*LAT+d] + bc[1]*W1[5*LAT+d]
                        + bc[2]*W1[6*LAT+d] + bc[3]*W1[7*LAT+d];
    if (d == 0) out[bn] = 0.0f;   // out has B*P=128 elems == gridDim
}

// ---------------- attention: one block per query -----------------------------
__global__ void __launch_bounds__(256) att_kernel(
    const float* __restrict__ phase, const float* __restrict__ pos_coords,
    const float* __restrict__ sigma, const float* __restrict__ vel_coords,
    const float* __restrict__ Wq, const float* __restrict__ bq,
    const float* __restrict__ Wk, const float* __restrict__ bk,
    const float* __restrict__ Wv, const float* __restrict__ bv,
    const float* __restrict__ Wo, const float* __restrict__ bo)
{
    __shared__ float vs[TT*33];
    __shared__ float lg[HH*TT];
    __shared__ float Wos[AO*AO];
    __shared__ float Wks[4*AO], Wqs[4*AO], Wvs[2*AO];
    __shared__ float bks[AO], bqs[AO], bvs[AO], bos[AO];
    __shared__ float qs[AO], part[8*AO], attns[AO];

    int tid = threadIdx.x;
    if (tid < 128)      { Wks[tid] = Wk[tid]; Wqs[tid] = Wq[tid]; }
    else if (tid < 192) { Wvs[tid-128] = Wv[tid-128]; }
    else if (tid < 224) { int j = tid-192; bks[j] = bk[j]; bqs[j] = bq[j]; }
    else                { int j = tid-224; bvs[j] = bv[j]; bos[j] = bo[j]; }
    for (int i = tid; i < AO*AO; i += 256) Wos[i] = Wo[i];

    int bid = blockIdx.x;
    int b; float c0, c1, c2, c3; float* outp;
    if (bid < BB*PP) {
        b = bid / PP; int p = bid % PP;
        const float* ph = phase + (b*PP+p)*4;
        c0 = ph[0]; c1 = ph[1]; c2 = ph[2]; c3 = ph[3];
        outp = g_att_main + (b*PP+p)*AO;
    } else {
        int idx = bid - BB*PP;
        b = idx / (PP*VV); int pv = idx % (PP*VV);
        int p = pv / VV, v = pv % VV;
        const float* ph = phase + (b*PP+p)*4;
        const float* vc = vel_coords + (b*VV+v)*2;
        c0 = ph[0]; c1 = ph[1]; c2 = vc[0]; c3 = vc[1];
        outp = g_att_self + ((b*PP+p)*VV+v)*AO;
    }
    __syncthreads();

    if (tid < AO)
        qs[tid] = c0*Wqs[tid] + c1*Wqs[AO+tid] + c2*Wqs[2*AO+tid] + c3*Wqs[3*AO+tid] + bqs[tid];

    int t = tid;
    const float* pc = pos_coords + (b*TT+t)*2;
    float r0 = pc[0] - c0, r1 = pc[1] - c1;
    bool valid = (r0*c2 + r1*c3) <= 0.0f;
    const float* sg = sigma + (b*TT+t)*2;
    float s0 = sg[0], s1 = sg[1];
    float kv[AO];
#pragma unroll
    for (int j = 0; j < AO; j++) {
        kv[j] = r0*Wks[j] + r1*Wks[AO+j] + c2*Wks[2*AO+j] + c3*Wks[3*AO+j] + bks[j];
        vs[t*33+j] = s0*Wvs[j] + s1*Wvs[AO+j] + bvs[j];
    }
    __syncthreads();
#pragma unroll
    for (int h = 0; h < HH; h++) {
        float l = 0.f;
#pragma unroll
        for (int d = 0; d < 8; d++) l += qs[h*8+d] * kv[h*8+d];
        lg[h*TT+t] = valid ? l * 0.3535533905932738f : -1e30f;
    }
    __syncthreads();

    int warp = tid >> 5, lane = tid & 31;
    if (warp < HH) {
        int h = warp;
        float mx = -1e38f;
#pragma unroll
        for (int i = 0; i < 8; i++) mx = fmaxf(mx, lg[h*TT+lane+32*i]);
#pragma unroll
        for (int o = 16; o; o >>= 1) mx = fmaxf(mx, __shfl_xor_sync(0xffffffffu, mx, o));
        float e[8]; float sm = 0.f;
#pragma unroll
        for (int i = 0; i < 8; i++) { e[i] = __expf(lg[h*TT+lane+32*i] - mx); sm += e[i]; }
#pragma unroll
        for (int o = 16; o; o >>= 1) sm += __shfl_xor_sync(0xffffffffu, sm, o);
        float inv = __fdividef(1.0f, sm);
#pragma unroll
        for (int i = 0; i < 8; i++) lg[h*TT+lane+32*i] = e[i] * inv;
    }
    __syncthreads();

    {
        int j = tid & 31, ch = tid >> 5, h = j >> 3;
        float s = 0.f; int t0 = ch * 32;
#pragma unroll
        for (int k = 0; k < 32; k++) s += lg[h*TT+t0+k] * vs[(t0+k)*33+j];
        part[ch*AO+j] = s;
    }
    __syncthreads();
    if (tid < AO) {
        float s = 0.f;
#pragma unroll
        for (int ch = 0; ch < 8; ch++) s += part[ch*AO+tid];
        attns[tid] = s;
    }
    __syncthreads();
    if (tid < AO) {
        float a = bos[tid];
#pragma unroll
        for (int j = 0; j < AO; j++) a += attns[j] * Wos[j*AO+tid];
        outp[tid] = __expf(-a);
    }
}

// ---------------- fused MLP + mixing + green + reduction ---------------------
__device__ __forceinline__ void mm64(const float* __restrict__ In,
                                     const float* __restrict__ W,
                                     const float* __restrict__ bias,
                                     float* __restrict__ Out,
                                     int r, int dg, bool act8, bool add)
{
    if (!act8) return;
    float acc[8];
#pragma unroll
    for (int i = 0; i < 8; i++) acc[i] = bias[dg+i];
    const float* inrow = In + r*RS;
    for (int c = 0; c < LAT; c += 4) {
        float4 x = *(const float4*)(inrow + c);
        const float* w = W + c*LAT + dg;
#pragma unroll
        for (int cc = 0; cc < 4; cc++) {
            float xv = (cc==0) ? x.x : (cc==1) ? x.y : (cc==2) ? x.z : x.w;
            float4 w0 = *(const float4*)(w + cc*LAT);
            float4 w1 = *(const float4*)(w + cc*LAT + 4);
            acc[0] += xv*w0.x; acc[1] += xv*w0.y; acc[2] += xv*w0.z; acc[3] += xv*w0.w;
            acc[4] += xv*w1.x; acc[5] += xv*w1.y; acc[6] += xv*w1.z; acc[7] += xv*w1.w;
        }
    }
    float* o = Out + r*RS + dg;
    if (add) {
#pragma unroll
        for (int i = 0; i < 8; i++) o[i] += tanh_fast(acc[i]);
    } else {
#pragma unroll
        for (int i = 0; i < 8; i++) o[i] = tanh_fast(acc[i]);
    }
}

__device__ __forceinline__ void mmix(const float* __restrict__ A,
                                     const float* __restrict__ SKs,
                                     float* __restrict__ Out,
                                     int r, int dg, bool act8)
{
    if (!act8) return;
    float acc[8];
#pragma unroll
    for (int i = 0; i < 8; i++) acc[i] = 0.f;
    const float* sk = SKs + r*33;
    for (int c = 0; c < VV; c++) {
        float xv = sk[c];
        const float* a = A + c*RS + dg;
        float4 a0 = *(const float4*)a;
        float4 a1 = *(const float4*)(a+4);
        acc[0] += xv*a0.x; acc[1] += xv*a0.y; acc[2] += xv*a0.z; acc[3] += xv*a0.w;
        acc[4] += xv*a1.x; acc[5] += xv*a1.y; acc[6] += xv*a1.z; acc[7] += xv*a1.w;
    }
    float* o = Out + r*RS + dg;
#pragma unroll
    for (int i = 0; i < 8; i++) o[i] = acc[i];
}

#define OFF_W1   0
#define OFF_W2   (OFF_W1 + 40*LAT)
#define OFF_WO   (OFF_W2 + LAT*LAT)
#define OFF_WS1  (OFF_WO + LAT*LAT)
#define OFF_WS2  (OFF_WS1 + LAT*LAT)
#define OFF_BV   (OFF_WS2 + LAT*LAT)
#define OFF_SK   (OFF_BV + 6*LAT)
#define OFF_B1   (OFF_SK + 1092)
#define OFF_X    (OFF_B1 + ROWS*RS)
#define OFF_Y    (OFF_X + ROWS*RS)
#define SMEM_FLOATS (OFF_Y + ROWS*RS)
#define SMEM_BYTES  (SMEM_FLOATS * 4)

__global__ void __launch_bounds__(288, 2) fused_kernel(
    const float* __restrict__ phase, const float* __restrict__ boundary,
    const float* __restrict__ bweights, const float* __restrict__ vel_coords,
    const float* __restrict__ vweights, const float* __restrict__ scat,
    const float* __restrict__ self_scat,
    const float* __restrict__ W1, const float* __restrict__ b1,
    const float* __restrict__ W2, const float* __restrict__ b2,
    const float* __restrict__ Wout, const float* __restrict__ bout,
    const float* __restrict__ Ws1, const float* __restrict__ bs1,
    const float* __restrict__ Ws2, const float* __restrict__ bs2,
    const float* __restrict__ Wp, float* __restrict__ out)
{
    extern __shared__ float sh[];
    float* W1s  = sh + OFF_W1;
    float* W2s  = sh + OFF_W2;
    float* Wos  = sh + OFF_WO;
    float* Ws1s = sh + OFF_WS1;
    float* Ws2s = sh + OFF_WS2;
    float* b1s  = sh + OFF_BV;
    float* b2s  = b1s + LAT;
    float* bouts= b1s + 2*LAT;
    float* bs1s = b1s + 3*LAT;
    float* bs2s = b1s + 4*LAT;
    float* Wps  = b1s + 5*LAT;
    float* SKs  = sh + OFF_SK;
    float* base1= sh + OFF_B1;
    float* Xb   = sh + OFF_X;
    float* Yb   = sh + OFF_Y;

    int tid = threadIdx.x;
    int bp = blockIdx.x >> 1;
    int half = blockIdx.x & 1;
    int b = bp / PP, p = bp % PP;

    for (int i = tid; i < 40*LAT; i += 288) W1s[i] = W1[i];
    for (int i = tid; i < LAT*LAT; i += 288) {
        W2s[i] = W2[i]; Wos[i] = Wout[i]; Ws1s[i] = Ws1[i]; Ws2s[i] = Ws2[i];
    }
    if (tid < LAT) {
        b1s[tid] = b1[tid]; b2s[tid] = b2[tid]; bouts[tid] = bout[tid];
        bs1s[tid] = bs1[tid]; bs2s[tid] = bs2[tid]; Wps[tid] = Wp[tid];
    }
    for (int i = tid; i < ROWS*VV; i += 288) {
        int r = i >> 5, v = i & 31;
        float w = vweights[b*VV+v];
        SKs[r*33+v] = (r < 32) ? (1.0f - self_scat[(b*VV+r)*VV+v]) * w
                               : (1.0f - scat[(b*PP+p)*VV+v]) * w;
    }
    __syncthreads();

    const float* ph = phase + (b*PP+p)*4;
    float p0 = ph[0], p1 = ph[1], p2 = ph[2], p3 = ph[3];
    for (int i = tid; i < ROWS*LAT; i += 288) {
        int r = i >> 6, d = i & 63;
        float cc2, cc3; const float* att;
        if (r < 32) {
            cc2 = vel_coords[(b*VV+r)*2]; cc3 = vel_coords[(b*VV+r)*2+1];
            att = g_att_self + ((b*PP+p)*VV+r)*AO;
        } else {
            cc2 = p2; cc3 = p3;
            att = g_att_main + (b*PP+p)*AO;
        }
        float s = b1s[d] + p0*W1s[d] + p1*W1s[LAT+d] + cc2*W1s[2*LAT+d] + cc3*W1s[3*LAT+d];
#pragma unroll 8
        for (int j = 0; j < AO; j++) s += att[j] * W1s[(8+j)*LAT+d];
        base1[r*RS+d] = s;
    }
    __syncthreads();

    int r, dg; bool act8;
    if (tid < 256)      { r = tid >> 3; dg = (tid & 7) << 3; act8 = true; }
    else if (tid < 264) { r = 32; dg = (tid - 256) << 3; act8 = true; }
    else                { r = 0; dg = 0; act8 = false; }

    float accOut = 0.f;
    int n0 = half * (NBB/2), n1 = n0 + NBB/2;
    for (int n = n0; n < n1; ++n) {
        const float* bt = g_bterm + (b*NBB+n)*LAT;
        if (act8) {
            const float* ba = base1 + r*RS + dg;
#pragma unroll
            for (int i = 0; i < 8; i++)
                Xb[r*RS+dg+i] = tanh_fast(ba[i] + bt[dg+i]);
        }
        __syncthreads();
        mm64(Xb, W2s, b2s,  Yb, r, dg, act8, false);
        __syncthreads();
        mm64(Yb, Wos, bouts, Xb, r, dg, act8, false);
        __syncthreads();
        mmix(Xb, SKs, Yb, r, dg, act8);
        __syncthreads();
        mm64(Yb, Ws1s, bs1s, Xb, r, dg, act8, true);
        __syncthreads();
        mmix(Xb, SKs, Yb, r, dg, act8);
        __syncthreads();
        mm64(Yb, Ws2s, bs2s, Xb, r, dg, act8, true);

        if (tid >= 256) {
            __syncwarp();
            int lane = tid - 256;
            float s = Xb[32*RS+lane]*Wps[lane] + Xb[32*RS+32+lane]*Wps[32+lane];
#pragma unroll
            for (int o = 16; o; o >>= 1) s += __shfl_xor_sync(0xffffffffu, s, o);
            if (lane == 0)
                accOut += __expf(s) * boundary[b*NBB+n] * bweights[b*NBB+n];
            __syncwarp();
        }
    }
    if (tid == 256) atomicAdd(&out[bp], accOut);
}

extern "C" void kernel_launch(void* const* d_in, const int* in_sizes, int n_in,
                              void* d_out, int out_size)
{
    const float* phase   = (const float*)d_in[0];
    const float* bcoords = (const float*)d_in[1];
    const float* boundary= (const float*)d_in[2];
    const float* bweights= (const float*)d_in[3];
    const float* poscrd  = (const float*)d_in[4];
    const float* sigma   = (const float*)d_in[5];
    const float* velcrd  = (const float*)d_in[6];
    const float* vweights= (const float*)d_in[7];
    const float* scat    = (const float*)d_in[8];
    const float* sscat   = (const float*)d_in[9];
    const float* Wq = (const float*)d_in[10]; const float* bq = (const float*)d_in[11];
    const float* Wk = (const float*)d_in[12]; const float* bk = (const float*)d_in[13];
    const float* Wv = (const float*)d_in[14]; const float* bv = (const float*)d_in[15];
    const float* Wo = (const float*)d_in[16]; const float* bo = (const float*)d_in[17];
    const float* W1 = (const float*)d_in[18]; const float* b1 = (const float*)d_in[19];
    const float* W2 = (const float*)d_in[20]; const float* b2 = (const float*)d_in[21];
    const float* Wout = (const float*)d_in[22]; const float* bout = (const float*)d_in[23];
    const float* Ws1 = (const float*)d_in[24]; const float* bs1 = (const float*)d_in[25];
    const float* Ws2 = (const float*)d_in[26]; const float* bs2 = (const float*)d_in[27];
    const float* Wp = (const float*)d_in[28];
    float* out = (float*)d_out;

    cudaFuncSetAttribute(fused_kernel,
                         cudaFuncAttributeMaxDynamicSharedMemorySize, SMEM_BYTES);

    prep_kernel<<<BB*NBB, LAT>>>(bcoords, W1, out);
    att_kernel<<<BB*PP + BB*PP*VV, 256>>>(phase, poscrd, sigma, velcrd,
                                          Wq, bq, Wk, bk, Wv, bv, Wo, bo);
    fused_kernel<<<2*BB*PP, 288, SMEM_BYTES>>>(
        phase, boundary, bweights, velcrd, vweights, scat, sscat,
        W1, b1, W2, b2, Wout, bout, Ws1, bs1, Ws2, bs2, Wp, out);
}

// round 5
// speedup vs baseline: 1.3590x; 1.3590x over previous
#include <cuda_runtime.h>
#include <math.h>

#define BB  2
#define PP  64
#define NBB 64
#define TT  256
#define VV  32
#define HH  4
#define AO  32
#define LAT 64
#define RS  68
#define ROWS 33

typedef unsigned long long ull;

__device__ float g_att_main[BB*PP*AO];
__device__ float g_att_self[BB*PP*VV*AO];
__device__ float g_bterm[BB*NBB*LAT];

__device__ __forceinline__ float tanh_fast(float x) {
    float e = __expf(2.0f * x);
    return 1.0f - __fdividef(2.0f, e + 1.0f);
}
__device__ __forceinline__ ull packdup(float x) {
    ull r; asm("mov.b64 %0,{%1,%1};" : "=l"(r) : "f"(x)); return r;
}
__device__ __forceinline__ void fma2(ull& d, ull a, ull b) {
    asm("fma.rn.f32x2 %0,%1,%2,%0;" : "+l"(d) : "l"(a), "l"(b));
}
__device__ __forceinline__ float2 unpk(ull a) {
    float2 f; asm("mov.b64 {%0,%1},%2;" : "=f"(f.x), "=f"(f.y) : "l"(a)); return f;
}

// ---------------- prep: boundary term of MLP layer-1 + zero output ----------
__global__ void prep_kernel(const float* __restrict__ bcoords,
                            const float* __restrict__ W1,
                            float* __restrict__ out) {
    int bn = blockIdx.x, d = threadIdx.x;
    const float* bc = bcoords + bn * 4;
    g_bterm[bn*LAT + d] = bc[0]*W1[4*LAT+d] + bc[1]*W1[5*LAT+d]
                        + bc[2]*W1[6*LAT+d] + bc[3]*W1[7*LAT+d];
    if (d == 0) out[bn] = 0.0f;
}

// ---------------- attention: one block per query -----------------------------
__global__ void __launch_bounds__(256) att_kernel(
    const float* __restrict__ phase, const float* __restrict__ pos_coords,
    const float* __restrict__ sigma, const float* __restrict__ vel_coords,
    const float* __restrict__ Wq, const float* __restrict__ bq,
    const float* __restrict__ Wk, const float* __restrict__ bk,
    const float* __restrict__ Wv, const float* __restrict__ bv,
    const float* __restrict__ Wo, const float* __restrict__ bo)
{
    __shared__ float vs[TT*33];
    __shared__ float lg[HH*TT];
    __shared__ float Wos[AO*AO];
    __shared__ float Wks[4*AO], Wqs[4*AO], Wvs[2*AO];
    __shared__ float bks[AO], bqs[AO], bvs[AO], bos[AO];
    __shared__ float qs[AO], part[8*AO], attns[AO];

    int tid = threadIdx.x;
    if (tid < 128)      { Wks[tid] = Wk[tid]; Wqs[tid] = Wq[tid]; }
    else if (tid < 192) { Wvs[tid-128] = Wv[tid-128]; }
    else if (tid < 224) { int j = tid-192; bks[j] = bk[j]; bqs[j] = bq[j]; }
    else                { int j = tid-224; bvs[j] = bv[j]; bos[j] = bo[j]; }
    for (int i = tid; i < AO*AO; i += 256) Wos[i] = Wo[i];

    int bid = blockIdx.x;
    int b; float c0, c1, c2, c3; float* outp;
    if (bid < BB*PP) {
        b = bid / PP; int p = bid % PP;
        const float* ph = phase + (b*PP+p)*4;
        c0 = ph[0]; c1 = ph[1]; c2 = ph[2]; c3 = ph[3];
        outp = g_att_main + (b*PP+p)*AO;
    } else {
        int idx = bid - BB*PP;
        b = idx / (PP*VV); int pv = idx % (PP*VV);
        int p = pv / VV, v = pv % VV;
        const float* ph = phase + (b*PP+p)*4;
        const float* vc = vel_coords + (b*VV+v)*2;
        c0 = ph[0]; c1 = ph[1]; c2 = vc[0]; c3 = vc[1];
        outp = g_att_self + ((b*PP+p)*VV+v)*AO;
    }
    __syncthreads();

    if (tid < AO)
        qs[tid] = c0*Wqs[tid] + c1*Wqs[AO+tid] + c2*Wqs[2*AO+tid] + c3*Wqs[3*AO+tid] + bqs[tid];

    int t = tid;
    const float* pc = pos_coords + (b*TT+t)*2;
    float r0 = pc[0] - c0, r1 = pc[1] - c1;
    bool valid = (r0*c2 + r1*c3) <= 0.0f;
    const float* sg = sigma + (b*TT+t)*2;
    float s0 = sg[0], s1 = sg[1];
    float kv[AO];
#pragma unroll
    for (int j = 0; j < AO; j++) {
        kv[j] = r0*Wks[j] + r1*Wks[AO+j] + c2*Wks[2*AO+j] + c3*Wks[3*AO+j] + bks[j];
        vs[t*33+j] = s0*Wvs[j] + s1*Wvs[AO+j] + bvs[j];
    }
    __syncthreads();
#pragma unroll
    for (int h = 0; h < HH; h++) {
        float l = 0.f;
#pragma unroll
        for (int d = 0; d < 8; d++) l += qs[h*8+d] * kv[h*8+d];
        lg[h*TT+t] = valid ? l * 0.3535533905932738f : -1e30f;
    }
    __syncthreads();

    int warp = tid >> 5, lane = tid & 31;
    if (warp < HH) {
        int h = warp;
        float mx = -1e38f;
#pragma unroll
        for (int i = 0; i < 8; i++) mx = fmaxf(mx, lg[h*TT+lane+32*i]);
#pragma unroll
        for (int o = 16; o; o >>= 1) mx = fmaxf(mx, __shfl_xor_sync(0xffffffffu, mx, o));
        float e[8]; float sm = 0.f;
#pragma unroll
        for (int i = 0; i < 8; i++) { e[i] = __expf(lg[h*TT+lane+32*i] - mx); sm += e[i]; }
#pragma unroll
        for (int o = 16; o; o >>= 1) sm += __shfl_xor_sync(0xffffffffu, sm, o);
        float inv = __fdividef(1.0f, sm);
#pragma unroll
        for (int i = 0; i < 8; i++) lg[h*TT+lane+32*i] = e[i] * inv;
    }
    __syncthreads();

    {
        int j = tid & 31, ch = tid >> 5, h = j >> 3;
        float s = 0.f; int t0 = ch * 32;
#pragma unroll
        for (int k = 0; k < 32; k++) s += lg[h*TT+t0+k] * vs[(t0+k)*33+j];
        part[ch*AO+j] = s;
    }
    __syncthreads();
    if (tid < AO) {
        float s = 0.f;
#pragma unroll
        for (int ch = 0; ch < 8; ch++) s += part[ch*AO+tid];
        attns[tid] = s;
    }
    __syncthreads();
    if (tid < AO) {
        float a = bos[tid];
#pragma unroll
        for (int j = 0; j < AO; j++) a += attns[j] * Wos[j*AO+tid];
        outp[tid] = __expf(-a);
    }
}

// ---------------- fused MLP + mixing + green + reduction ---------------------
__device__ __forceinline__ void gemm_row(const float* __restrict__ In,
                                         const float* __restrict__ W,
                                         const float* __restrict__ bias,
                                         int r, int dg, float o[8])
{
    const ulonglong2* bp = (const ulonglong2*)(bias + dg);
    ulonglong2 b01 = bp[0], b23 = bp[1];
    ull a0 = b01.x, a1 = b01.y, a2 = b23.x, a3 = b23.y;
    const float* inrow = In + r*RS;
#pragma unroll 4
    for (int c = 0; c < LAT; c += 4) {
        float4 x = *(const float4*)(inrow + c);
#pragma unroll
        for (int cc = 0; cc < 4; cc++) {
            float xv = (cc==0) ? x.x : (cc==1) ? x.y : (cc==2) ? x.z : x.w;
            ull x2 = packdup(xv);
            const ulonglong2* w = (const ulonglong2*)(W + (c+cc)*LAT + dg);
            ulonglong2 w01 = w[0], w23 = w[1];
            fma2(a0, x2, w01.x); fma2(a1, x2, w01.y);
            fma2(a2, x2, w23.x); fma2(a3, x2, w23.y);
        }
    }
    float2 f0 = unpk(a0), f1 = unpk(a1), f2 = unpk(a2), f3 = unpk(a3);
    o[0]=f0.x; o[1]=f0.y; o[2]=f1.x; o[3]=f1.y;
    o[4]=f2.x; o[5]=f2.y; o[6]=f3.x; o[7]=f3.y;
}

__device__ __forceinline__ void mix_row(const float* __restrict__ A,
                                        const float* __restrict__ sk,
                                        int dg, float o[8])
{
    ull a0=0, a1=0, a2=0, a3=0;
#pragma unroll 4
    for (int c = 0; c < VV; c++) {
        ull x2 = packdup(sk[c]);
        const ulonglong2* a = (const ulonglong2*)(A + c*RS + dg);
        ulonglong2 a01 = a[0], a23 = a[1];
        fma2(a0, x2, a01.x); fma2(a1, x2, a01.y);
        fma2(a2, x2, a23.x); fma2(a3, x2, a23.y);
    }
    float2 f0 = unpk(a0), f1 = unpk(a1), f2 = unpk(a2), f3 = unpk(a3);
    o[0]=f0.x; o[1]=f0.y; o[2]=f1.x; o[3]=f1.y;
    o[4]=f2.x; o[5]=f2.y; o[6]=f3.x; o[7]=f3.y;
}

#define OFF_W1   0
#define OFF_W2   (OFF_W1 + 40*LAT)
#define OFF_WO   (OFF_W2 + LAT*LAT)
#define OFF_WS1  (OFF_WO + LAT*LAT)
#define OFF_WS2  (OFF_WS1 + LAT*LAT)
#define OFF_BV   (OFF_WS2 + LAT*LAT)
#define OFF_SK   (OFF_BV + 6*LAT)
#define OFF_B1   (OFF_SK + 1092)
#define OFF_X    (OFF_B1 + ROWS*RS)
#define OFF_Y    (OFF_X + ROWS*RS)
#define SMEM_FLOATS (OFF_Y + ROWS*RS)
#define SMEM_BYTES  (SMEM_FLOATS * 4)

__global__ void __launch_bounds__(288, 2) fused_kernel(
    const float* __restrict__ phase, const float* __restrict__ boundary,
    const float* __restrict__ bweights, const float* __restrict__ vel_coords,
    const float* __restrict__ vweights, const float* __restrict__ scat,
    const float* __restrict__ self_scat,
    const float* __restrict__ W1, const float* __restrict__ b1,
    const float* __restrict__ W2, const float* __restrict__ b2,
    const float* __restrict__ Wout, const float* __restrict__ bout,
    const float* __restrict__ Ws1, const float* __restrict__ bs1,
    const float* __restrict__ Ws2, const float* __restrict__ bs2,
    const float* __restrict__ Wp, float* __restrict__ out)
{
    extern __shared__ float sh[];
    float* W1s  = sh + OFF_W1;
    float* W2s  = sh + OFF_W2;
    float* Wos  = sh + OFF_WO;
    float* Ws1s = sh + OFF_WS1;
    float* Ws2s = sh + OFF_WS2;
    float* b1s  = sh + OFF_BV;
    float* b2s  = b1s + LAT;
    float* bouts= b1s + 2*LAT;
    float* bs1s = b1s + 3*LAT;
    float* bs2s = b1s + 4*LAT;
    float* Wps  = b1s + 5*LAT;
    float* SKs  = sh + OFF_SK;
    float* base1= sh + OFF_B1;
    float* Xb   = sh + OFF_X;
    float* Yb   = sh + OFF_Y;

    int tid = threadIdx.x;
    int bp = blockIdx.x >> 1;
    int half = blockIdx.x & 1;
    int b = bp / PP, p = bp % PP;
    int n0 = half * (NBB/2);

    for (int i = tid; i < 40*LAT; i += 288) W1s[i] = W1[i];
    for (int i = tid; i < LAT*LAT; i += 288) {
        W2s[i] = W2[i]; Wos[i] = Wout[i]; Ws1s[i] = Ws1[i]; Ws2s[i] = Ws2[i];
    }
    if (tid < LAT) {
        b1s[tid] = b1[tid]; b2s[tid] = b2[tid]; bouts[tid] = bout[tid];
        bs1s[tid] = bs1[tid]; bs2s[tid] = bs2[tid]; Wps[tid] = Wp[tid];
    }
    for (int i = tid; i < ROWS*VV; i += 288) {
        int rr = i >> 5, v = i & 31;
        float w = vweights[b*VV+v];
        SKs[rr*33+v] = (rr < 32) ? (1.0f - self_scat[(b*VV+rr)*VV+v]) * w
                                 : (1.0f - scat[(b*PP+p)*VV+v]) * w;
    }
    __syncthreads();

    const float* ph = phase + (b*PP+p)*4;
    float p0 = ph[0], p1 = ph[1], p2 = ph[2], p3 = ph[3];
    for (int i = tid; i < ROWS*LAT; i += 288) {
        int rr = i >> 6, d = i & 63;
        float cc2, cc3; const float* att;
        if (rr < 32) {
            cc2 = vel_coords[(b*VV+rr)*2]; cc3 = vel_coords[(b*VV+rr)*2+1];
            att = g_att_self + ((b*PP+p)*VV+rr)*AO;
        } else {
            cc2 = p2; cc3 = p3;
            att = g_att_main + (b*PP+p)*AO;
        }
        float s = b1s[d] + p0*W1s[d] + p1*W1s[LAT+d] + cc2*W1s[2*LAT+d] + cc3*W1s[3*LAT+d];
#pragma unroll 8
        for (int j = 0; j < AO; j++) s += att[j] * W1s[(8+j)*LAT+d];
        base1[rr*RS+d] = s;
    }
    __syncthreads();

    float* btS = W1s;
    for (int i = tid; i < (NBB/2)*LAT; i += 288)
        btS[i] = g_bterm[(b*NBB + n0 + (i >> 6))*LAT + (i & 63)];

    int r, dg; bool act8;
    if (tid < 256)      { r = tid >> 3; dg = (tid & 7) << 3; act8 = true; }
    else if (tid < 264) { r = 32; dg = (tid - 256) << 3; act8 = true; }
    else                { r = 0; dg = 0; act8 = false; }
    int lane8 = tid - 256;

    float accOut = 0.f;
    for (int nl = 0; nl < NBB/2; ++nl) {
        __syncthreads();                 // btS ready / Xb free of warp-8 trailing reads
        const float* bt = btS + nl*LAT;
        if (act8) {
#pragma unroll
            for (int i = 0; i < 8; i++)
                Xb[r*RS+dg+i] = tanh_fast(base1[r*RS+dg+i] + bt[dg+i]);
        }
        __syncwarp();
        if (act8) {                      // layer 2 (row-local)
            float o[8]; gemm_row(Xb, W2s, b2s, r, dg, o);
#pragma unroll
            for (int i = 0; i < 8; i++) Yb[r*RS+dg+i] = tanh_fast(o[i]);
        }
        __syncwarp();
        if (act8) {                      // layer 3 (row-local)
            float o[8]; gemm_row(Yb, Wos, bouts, r, dg, o);
#pragma unroll
            for (int i = 0; i < 8; i++) Xb[r*RS+dg+i] = tanh_fast(o[i]);
        }
        __syncthreads();                 // full tile visible for mix 1
        if (act8) {
            float m[8]; mix_row(Xb, SKs + r*33, dg, m);
#pragma unroll
            for (int i = 0; i < 8; i++) Yb[r*RS+dg+i] = m[i];
        }
        __syncthreads();                 // ALL mix1 reads of Xb done before Ws1 writes Xb (R4 bugfix)
        if (act8) {                      // Ws1 update (row-local, +=)
            float o[8]; gemm_row(Yb, Ws1s, bs1s, r, dg, o);
#pragma unroll
            for (int i = 0; i < 8; i++) Xb[r*RS+dg+i] += tanh_fast(o[i]);
        }
        __syncthreads();                 // post-Ws1 tile visible for warp-8 mix 2

        // only row 32 survives mixing iter 2 -> warp 8 finishes alone
        if (tid >= 256) {
            if (lane8 < 8) {
                int d8 = lane8 << 3;
                float m[8]; mix_row(Xb, SKs + 32*33, d8, m);
#pragma unroll
                for (int i = 0; i < 8; i++) Yb[32*RS+d8+i] = m[i];
            }
            __syncwarp();
            if (lane8 < 8) {
                int d8 = lane8 << 3;
                float o[8]; gemm_row(Yb, Ws2s, bs2s, 32, d8, o);
                float s = 0.f;
#pragma unroll
                for (int i = 0; i < 8; i++)
                    s += (Xb[32*RS+d8+i] + tanh_fast(o[i])) * Wps[d8+i];
                s += __shfl_xor_sync(0xffu, s, 1);
                s += __shfl_xor_sync(0xffu, s, 2);
                s += __shfl_xor_sync(0xffu, s, 4);
                if (lane8 == 0) {
                    int n = n0 + nl;
                    accOut += __expf(s) * boundary[b*NBB+n] * bweights[b*NBB+n];
                }
            }
        }
    }
    if (tid == 256) atomicAdd(&out[bp], accOut);
}

extern "C" void kernel_launch(void* const* d_in, const int* in_sizes, int n_in,
                              void* d_out, int out_size)
{
    const float* phase   = (const float*)d_in[0];
    const float* bcoords = (const float*)d_in[1];
    const float* boundary= (const float*)d_in[2];
    const float* bweights= (const float*)d_in[3];
    const float* poscrd  = (const float*)d_in[4];
    const float* sigma   = (const float*)d_in[5];
    const float* velcrd  = (const float*)d_in[6];
    const float* vweights= (const float*)d_in[7];
    const float* scat    = (const float*)d_in[8];
    const float* sscat   = (const float*)d_in[9];
    const float* Wq = (const float*)d_in[10]; const float* bq = (const float*)d_in[11];
    const float* Wk = (const float*)d_in[12]; const float* bk = (const float*)d_in[13];
    const float* Wv = (const float*)d_in[14]; const float* bv = (const float*)d_in[15];
    const float* Wo = (const float*)d_in[16]; const float* bo = (const float*)d_in[17];
    const float* W1 = (const float*)d_in[18]; const float* b1 = (const float*)d_in[19];
    const float* W2 = (const float*)d_in[20]; const float* b2 = (const float*)d_in[21];
    const float* Wout = (const float*)d_in[22]; const float* bout = (const float*)d_in[23];
    const float* Ws1 = (const float*)d_in[24]; const float* bs1 = (const float*)d_in[25];
    const float* Ws2 = (const float*)d_in[26]; const float* bs2 = (const float*)d_in[27];
    const float* Wp = (const float*)d_in[28];
    float* out = (float*)d_out;

    cudaFuncSetAttribute(fused_kernel,
                         cudaFuncAttributeMaxDynamicSharedMemorySize, SMEM_BYTES);

    prep_kernel<<<BB*NBB, LAT>>>(bcoords, W1, out);
    att_kernel<<<BB*PP + BB*PP*VV, 256>>>(phase, poscrd, sigma, velcrd,
                                          Wq, bq, Wk, bk, Wv, bv, Wo, bo);
    fused_kernel<<<2*BB*PP, 288, SMEM_BYTES>>>(
        phase, boundary, bweights, velcrd, vweights, scat, sscat,
        W1, b1, W2, b2, Wout, bout, Ws1, bs1, Ws2, bs2, Wp, out);
}

// round 7
// speedup vs baseline: 1.3602x; 1.0009x over previous
#include <cuda_runtime.h>
#include <math.h>

#define BB  2
#define PP  64
#define NBB 64
#define TT  256
#define VV  32
#define HH  4
#define AO  32
#define LAT 64
#define RS  68
#define ROWS 33

typedef unsigned long long ull;

__device__ float g_att_main[BB*PP*AO];
__device__ float g_att_self[BB*PP*VV*AO];
__device__ float g_bterm[BB*NBB*LAT];

__device__ __forceinline__ float tanh_fast(float x) {
    float e = __expf(2.0f * x);
    return 1.0f - __fdividef(2.0f, e + 1.0f);
}
__device__ __forceinline__ ull packdup(float x) {
    ull r; asm("mov.b64 %0,{%1,%1};" : "=l"(r) : "f"(x)); return r;
}
__device__ __forceinline__ void fma2(ull& d, ull a, ull b) {
    asm("fma.rn.f32x2 %0,%1,%2,%0;" : "+l"(d) : "l"(a), "l"(b));
}
__device__ __forceinline__ float2 unpk(ull a) {
    float2 f; asm("mov.b64 {%0,%1},%2;" : "=f"(f.x), "=f"(f.y) : "l"(a)); return f;
}

// ---------------- attention (+ absorbed prep) --------------------------------
__global__ void __launch_bounds__(256) att_kernel(
    const float* __restrict__ phase, const float* __restrict__ pos_coords,
    const float* __restrict__ sigma, const float* __restrict__ vel_coords,
    const float* __restrict__ Wq, const float* __restrict__ bq,
    const float* __restrict__ Wk, const float* __restrict__ bk,
    const float* __restrict__ Wv, const float* __restrict__ bv,
    const float* __restrict__ Wo, const float* __restrict__ bo,
    const float* __restrict__ bcoords, const float* __restrict__ W1,
    float* __restrict__ out)
{
    __shared__ float vs[TT*33];
    __shared__ float lg[HH*TT];
    __shared__ float Wos[AO*AO];
    __shared__ float Wks[4*AO], Wqs[4*AO], Wvs[2*AO];
    __shared__ float bks[AO], bqs[AO], bvs[AO], bos[AO];
    __shared__ float qs[AO], part[8*AO], attns[AO];

    int tid = threadIdx.x;
    int bid = blockIdx.x;

    // absorbed prep: blocks 0..BB*NBB-1 compute bterm row + zero out
    if (bid < BB*NBB) {
        if (tid < LAT) {
            const float* bc = bcoords + bid * 4;
            g_bterm[bid*LAT + tid] = bc[0]*W1[4*LAT+tid] + bc[1]*W1[5*LAT+tid]
                                   + bc[2]*W1[6*LAT+tid] + bc[3]*W1[7*LAT+tid];
        }
        if (tid == 0) out[bid] = 0.0f;   // out has BB*PP = BB*NBB = 128 elems
    }

    if (tid < 128)      { Wks[tid] = Wk[tid]; Wqs[tid] = Wq[tid]; }
    else if (tid < 192) { Wvs[tid-128] = Wv[tid-128]; }
    else if (tid < 224) { int j = tid-192; bks[j] = bk[j]; bqs[j] = bq[j]; }
    else                { int j = tid-224; bvs[j] = bv[j]; bos[j] = bo[j]; }
    for (int i = tid; i < AO*AO; i += 256) Wos[i] = Wo[i];

    int b; float c0, c1, c2, c3; float* outp;
    if (bid < BB*PP) {
        b = bid / PP; int p = bid % PP;
        const float* ph = phase + (b*PP+p)*4;
        c0 = ph[0]; c1 = ph[1]; c2 = ph[2]; c3 = ph[3];
        outp = g_att_main + (b*PP+p)*AO;
    } else {
        int idx = bid - BB*PP;
        b = idx / (PP*VV); int pv = idx % (PP*VV);
        int p = pv / VV, v = pv % VV;
        const float* ph = phase + (b*PP+p)*4;
        const float* vc = vel_coords + (b*VV+v)*2;
        c0 = ph[0]; c1 = ph[1]; c2 = vc[0]; c3 = vc[1];
        outp = g_att_self + ((b*PP+p)*VV+v)*AO;
    }
    __syncthreads();

    if (tid < AO)
        qs[tid] = c0*Wqs[tid] + c1*Wqs[AO+tid] + c2*Wqs[2*AO+tid] + c3*Wqs[3*AO+tid] + bqs[tid];

    int t = tid;
    const float* pc = pos_coords + (b*TT+t)*2;
    float r0 = pc[0] - c0, r1 = pc[1] - c1;
    bool valid = (r0*c2 + r1*c3) <= 0.0f;
    const float* sg = sigma + (b*TT+t)*2;
    float s0 = sg[0], s1 = sg[1];
    float kv[AO];
#pragma unroll
    for (int j = 0; j < AO; j++) {
        kv[j] = r0*Wks[j] + r1*Wks[AO+j] + c2*Wks[2*AO+j] + c3*Wks[3*AO+j] + bks[j];
        vs[t*33+j] = s0*Wvs[j] + s1*Wvs[AO+j] + bvs[j];
    }
    __syncthreads();
#pragma unroll
    for (int h = 0; h < HH; h++) {
        float l = 0.f;
#pragma unroll
        for (int d = 0; d < 8; d++) l += qs[h*8+d] * kv[h*8+d];
        lg[h*TT+t] = valid ? l * 0.3535533905932738f : -1e30f;
    }
    __syncthreads();

    int warp = tid >> 5, lane = tid & 31;
    if (warp < HH) {
        int h = warp;
        float mx = -1e38f;
#pragma unroll
        for (int i = 0; i < 8; i++) mx = fmaxf(mx, lg[h*TT+lane+32*i]);
#pragma unroll
        for (int o = 16; o; o >>= 1) mx = fmaxf(mx, __shfl_xor_sync(0xffffffffu, mx, o));
        float e[8]; float sm = 0.f;
#pragma unroll
        for (int i = 0; i < 8; i++) { e[i] = __expf(lg[h*TT+lane+32*i] - mx); sm += e[i]; }
#pragma unroll
        for (int o = 16; o; o >>= 1) sm += __shfl_xor_sync(0xffffffffu, sm, o);
        float inv = __fdividef(1.0f, sm);
#pragma unroll
        for (int i = 0; i < 8; i++) lg[h*TT+lane+32*i] = e[i] * inv;
    }
    __syncthreads();

    {
        int j = tid & 31, ch = tid >> 5, h = j >> 3;
        float s = 0.f; int t0 = ch * 32;
#pragma unroll
        for (int k = 0; k < 32; k++) s += lg[h*TT+t0+k] * vs[(t0+k)*33+j];
        part[ch*AO+j] = s;
    }
    __syncthreads();
    if (tid < AO) {
        float s = 0.f;
#pragma unroll
        for (int ch = 0; ch < 8; ch++) s += part[ch*AO+tid];
        attns[tid] = s;
    }
    __syncthreads();
    if (tid < AO) {
        float a = bos[tid];
#pragma unroll
        for (int j = 0; j < AO; j++) a += attns[j] * Wos[j*AO+tid];
        outp[tid] = __expf(-a);
    }
}

// ---------------- fused MLP + mixing + green + reduction ---------------------
__device__ __forceinline__ void gemm_row(const float* __restrict__ In,
                                         const float* __restrict__ W,
                                         const float* __restrict__ bias,
                                         int r, int dg, float o[8])
{
    const ulonglong2* bp = (const ulonglong2*)(bias + dg);
    ulonglong2 b01 = bp[0], b23 = bp[1];
    ull a0 = b01.x, a1 = b01.y, a2 = b23.x, a3 = b23.y;
    const float* inrow = In + r*RS;
#pragma unroll 4
    for (int c = 0; c < LAT; c += 4) {
        float4 x = *(const float4*)(inrow + c);
#pragma unroll
        for (int cc = 0; cc < 4; cc++) {
            float xv = (cc==0) ? x.x : (cc==1) ? x.y : (cc==2) ? x.z : x.w;
            ull x2 = packdup(xv);
            const ulonglong2* w = (const ulonglong2*)(W + (c+cc)*LAT + dg);
            ulonglong2 w01 = w[0], w23 = w[1];
            fma2(a0, x2, w01.x); fma2(a1, x2, w01.y);
            fma2(a2, x2, w23.x); fma2(a3, x2, w23.y);
        }
    }
    float2 f0 = unpk(a0), f1 = unpk(a1), f2 = unpk(a2), f3 = unpk(a3);
    o[0]=f0.x; o[1]=f0.y; o[2]=f1.x; o[3]=f1.y;
    o[4]=f2.x; o[5]=f2.y; o[6]=f3.x; o[7]=f3.y;
}

__device__ __forceinline__ void mix_row(const float* __restrict__ A,
                                        const float* __restrict__ sk,
                                        int dg, float o[8])
{
    ull a0=0, a1=0, a2=0, a3=0;
#pragma unroll 4
    for (int c = 0; c < VV; c++) {
        ull x2 = packdup(sk[c]);
        const ulonglong2* a = (const ulonglong2*)(A + c*RS + dg);
        ulonglong2 a01 = a[0], a23 = a[1];
        fma2(a0, x2, a01.x); fma2(a1, x2, a01.y);
        fma2(a2, x2, a23.x); fma2(a3, x2, a23.y);
    }
    float2 f0 = unpk(a0), f1 = unpk(a1), f2 = unpk(a2), f3 = unpk(a3);
    o[0]=f0.x; o[1]=f0.y; o[2]=f1.x; o[3]=f1.y;
    o[4]=f2.x; o[5]=f2.y; o[6]=f3.x; o[7]=f3.y;
}

#define OFF_W1   0
#define OFF_W2   (OFF_W1 + 40*LAT)
#define OFF_WO   (OFF_W2 + LAT*LAT)
#define OFF_WS1  (OFF_WO + LAT*LAT)
#define OFF_WS2  (OFF_WS1 + LAT*LAT)
#define OFF_BV   (OFF_WS2 + LAT*LAT)
#define OFF_WQ   (OFF_BV + 6*LAT)
#define OFF_SK   (OFF_WQ + 32)
#define OFF_B1   (OFF_SK + 1092)
#define OFF_X    (OFF_B1 + ROWS*RS)
#define OFF_Y    (OFF_X + ROWS*RS)
#define SMEM_FLOATS (OFF_Y + ROWS*RS)
#define SMEM_BYTES  (SMEM_FLOATS * 4)

__global__ void __launch_bounds__(288, 2) fused_kernel(
    const float* __restrict__ phase, const float* __restrict__ boundary,
    const float* __restrict__ bweights, const float* __restrict__ vel_coords,
    const float* __restrict__ vweights, const float* __restrict__ scat,
    const float* __restrict__ self_scat,
    const float* __restrict__ W1, const float* __restrict__ b1,
    const float* __restrict__ W2, const float* __restrict__ b2,
    const float* __restrict__ Wout, const float* __restrict__ bout,
    const float* __restrict__ Ws1, const float* __restrict__ bs1,
    const float* __restrict__ Ws2, const float* __restrict__ bs2,
    const float* __restrict__ Wp, float* __restrict__ out)
{
    extern __shared__ float sh[];
    float* W1s  = sh + OFF_W1;
    float* W2s  = sh + OFF_W2;
    float* Wos  = sh + OFF_WO;
    float* Ws1s = sh + OFF_WS1;
    float* Ws2s = sh + OFF_WS2;
    float* b1s  = sh + OFF_BV;
    float* b2s  = b1s + LAT;
    float* bouts= b1s + 2*LAT;
    float* bs1s = b1s + 3*LAT;
    float* bs2s = b1s + 4*LAT;
    float* Wps  = b1s + 5*LAT;
    float* wqS  = sh + OFF_WQ;
    float* SKs  = sh + OFF_SK;
    float* base1= sh + OFF_B1;
    float* Xb   = sh + OFF_X;
    float* Yb   = sh + OFF_Y;

    int tid = threadIdx.x;
    int bp = blockIdx.x >> 1;
    int half = blockIdx.x & 1;
    int b = bp / PP, p = bp % PP;
    int n0 = half * (NBB/2);

    for (int i = tid; i < 40*LAT; i += 288) W1s[i] = W1[i];
    for (int i = tid; i < LAT*LAT; i += 288) {
        W2s[i] = W2[i]; Wos[i] = Wout[i]; Ws1s[i] = Ws1[i]; Ws2s[i] = Ws2[i];
    }
    if (tid < LAT) {
        b1s[tid] = b1[tid]; b2s[tid] = b2[tid]; bouts[tid] = bout[tid];
        bs1s[tid] = bs1[tid]; bs2s[tid] = bs2[tid]; Wps[tid] = Wp[tid];
    }
    if (tid < NBB/2) {
        int n = n0 + tid;
        wqS[tid] = boundary[b*NBB+n] * bweights[b*NBB+n];
    }
    for (int i = tid; i < ROWS*VV; i += 288) {
        int rr = i >> 5, v = i & 31;
        float w = vweights[b*VV+v];
        SKs[rr*33+v] = (rr < 32) ? (1.0f - self_scat[(b*VV+rr)*VV+v]) * w
                                 : (1.0f - scat[(b*PP+p)*VV+v]) * w;
    }
    __syncthreads();

    const float* ph = phase + (b*PP+p)*4;
    float p0 = ph[0], p1 = ph[1], p2 = ph[2], p3 = ph[3];
    for (int i = tid; i < ROWS*LAT; i += 288) {
        int rr = i >> 6, d = i & 63;
        float cc2, cc3; const float* att;
        if (rr < 32) {
            cc2 = vel_coords[(b*VV+rr)*2]; cc3 = vel_coords[(b*VV+rr)*2+1];
            att = g_att_self + ((b*PP+p)*VV+rr)*AO;
        } else {
            cc2 = p2; cc3 = p3;
            att = g_att_main + (b*PP+p)*AO;
        }
        float s = b1s[d] + p0*W1s[d] + p1*W1s[LAT+d] + cc2*W1s[2*LAT+d] + cc3*W1s[3*LAT+d];
#pragma unroll 8
        for (int j = 0; j < AO; j++) s += att[j] * W1s[(8+j)*LAT+d];
        base1[rr*RS+d] = s;
    }
    __syncthreads();

    float* btS = W1s;                  // W1s dead after prologue
    for (int i = tid; i < (NBB/2)*LAT; i += 288)
        btS[i] = g_bterm[(b*NBB + n0 + (i >> 6))*LAT + (i & 63)];

    int r, dg; bool act8;
    if (tid < 256)      { r = tid >> 3; dg = (tid & 7) << 3; act8 = true; }
    else if (tid < 264) { r = 32; dg = (tid - 256) << 3; act8 = true; }
    else                { r = 0; dg = 0; act8 = false; }
    int lane8 = tid - 256;

    float accOut = 0.f;
    for (int nl = 0; nl < NBB/2; ++nl) {
        __syncthreads();                 // btS/wqS ready; Xb free of warp-8 trailing reads
        const float* bt = btS + nl*LAT;
        if (act8) {
#pragma unroll
            for (int i = 0; i < 8; i++)
                Xb[r*RS+dg+i] = tanh_fast(base1[r*RS+dg+i] + bt[dg+i]);
        }
        __syncwarp();
        if (act8) {                      // layer 2 (row-local)
            float o[8]; gemm_row(Xb, W2s, b2s, r, dg, o);
#pragma unroll
            for (int i = 0; i < 8; i++) Yb[r*RS+dg+i] = tanh_fast(o[i]);
        }
        __syncwarp();
        if (act8) {                      // layer 3 (row-local)
            float o[8]; gemm_row(Yb, Wos, bouts, r, dg, o);
#pragma unroll
            for (int i = 0; i < 8; i++) Xb[r*RS+dg+i] = tanh_fast(o[i]);
        }
        __syncthreads();                 // full tile visible for mix 1
        if (act8) {
            float m[8]; mix_row(Xb, SKs + r*33, dg, m);
#pragma unroll
            for (int i = 0; i < 8; i++) Yb[r*RS+dg+i] = m[i];
        }
        __syncthreads();                 // all mix1 reads of Xb done before Ws1 writes Xb
        if (act8) {                      // Ws1 update (row-local, +=)
            float o[8]; gemm_row(Yb, Ws1s, bs1s, r, dg, o);
#pragma unroll
            for (int i = 0; i < 8; i++) Xb[r*RS+dg+i] += tanh_fast(o[i]);
        }
        __syncthreads();                 // post-Ws1 tile visible for warp-8 mix 2

        if (tid >= 256) {
            if (lane8 < 8) {
                int d8 = lane8 << 3;
                float m[8]; mix_row(Xb, SKs + 32*33, d8, m);
#pragma unroll
                for (int i = 0; i < 8; i++) Yb[32*RS+d8+i] = m[i];
            }
            __syncwarp();
            if (lane8 < 8) {
                int d8 = lane8 << 3;
                float o[8]; gemm_row(Yb, Ws2s, bs2s, 32, d8, o);
                float s = 0.f;
#pragma unroll
                for (int i = 0; i < 8; i++)
                    s += (Xb[32*RS+d8+i] + tanh_fast(o[i])) * Wps[d8+i];
                s += __shfl_xor_sync(0xffu, s, 1);
                s += __shfl_xor_sync(0xffu, s, 2);
                s += __shfl_xor_sync(0xffu, s, 4);
                if (lane8 == 0)
                    accOut += __expf(s) * wqS[nl];
            }
        }
    }
    if (tid == 256) atomicAdd(&out[bp], accOut);
}

extern "C" void kernel_launch(void* const* d_in, const int* in_sizes, int n_in,
                              void* d_out, int out_size)
{
    const float* phase   = (const float*)d_in[0];
    const float* bcoords = (const float*)d_in[1];
    const float* boundary= (const float*)d_in[2];
    const float* bweights= (const float*)d_in[3];
    const float* poscrd  = (const float*)d_in[4];
    const float* sigma   = (const float*)d_in[5];
    const float* velcrd  = (const float*)d_in[6];
    const float* vweights= (const float*)d_in[7];
    const float* scat    = (const float*)d_in[8];
    const float* sscat   = (const float*)d_in[9];
    const float* Wq = (const float*)d_in[10]; const float* bq = (const float*)d_in[11];
    const float* Wk = (const float*)d_in[12]; const float* bk = (const float*)d_in[13];
    const float* Wv = (const float*)d_in[14]; const float* bv = (const float*)d_in[15];
    const float* Wo = (const float*)d_in[16]; const float* bo = (const float*)d_in[17];
    const float* W1 = (const float*)d_in[18]; const float* b1 = (const float*)d_in[19];
    const float* W2 = (const float*)d_in[20]; const float* b2 = (const float*)d_in[21];
    const float* Wout = (const float*)d_in[22]; const float* bout = (const float*)d_in[23];
    const float* Ws1 = (const float*)d_in[24]; const float* bs1 = (const float*)d_in[25];
    const float* Ws2 = (const float*)d_in[26]; const float* bs2 = (const float*)d_in[27];
    const float* Wp = (const float*)d_in[28];
    float* out = (float*)d_out;

    cudaFuncSetAttribute(fused_kernel,
                         cudaFuncAttributeMaxDynamicSharedMemorySize, SMEM_BYTES);

    att_kernel<<<BB*PP + BB*PP*VV, 256>>>(phase, poscrd, sigma, velcrd,
                                          Wq, bq, Wk, bk, Wv, bv, Wo, bo,
                                          bcoords, W1, out);
    fused_kernel<<<2*BB*PP, 288, SMEM_BYTES>>>(
        phase, boundary, bweights, velcrd, vweights, scat, sscat,
        W1, b1, W2, b2, Wout, bout, Ws1, bs1, Ws2, bs2, Wp, out);
}

// round 8
// speedup vs baseline: 2.8910x; 2.1254x over previous
#include <cuda_runtime.h>
#include <math.h>

#define BB  2
#define PP  64
#define NBB 64
#define TT  256
#define VV  32
#define HH  4
#define AO  32
#define LAT 64
#define RS  68
#define ROWS 33
#define TS  (ROWS*RS)   // 2244 floats per tile

typedef unsigned long long ull;

__device__ float g_att_main[BB*PP*AO];
__device__ float g_att_self[BB*PP*VV*AO];
__device__ float g_bterm[BB*NBB*LAT];

__device__ __forceinline__ float tanh_fast(float x) {
    float e = __expf(2.0f * x);
    return 1.0f - __fdividef(2.0f, e + 1.0f);
}
__device__ __forceinline__ ull packdup(float x) {
    ull r; asm("mov.b64 %0,{%1,%1};" : "=l"(r) : "f"(x)); return r;
}
__device__ __forceinline__ void fma2(ull& d, ull a, ull b) {
    asm("fma.rn.f32x2 %0,%1,%2,%0;" : "+l"(d) : "l"(a), "l"(b));
}
__device__ __forceinline__ float2 unpk(ull a) {
    float2 f; asm("mov.b64 {%0,%1},%2;" : "=f"(f.x), "=f"(f.y) : "l"(a)); return f;
}

// ---------------- attention (+ absorbed prep) --------------------------------
__global__ void __launch_bounds__(256) att_kernel(
    const float* __restrict__ phase, const float* __restrict__ pos_coords,
    const float* __restrict__ sigma, const float* __restrict__ vel_coords,
    const float* __restrict__ Wq, const float* __restrict__ bq,
    const float* __restrict__ Wk, const float* __restrict__ bk,
    const float* __restrict__ Wv, const float* __restrict__ bv,
    const float* __restrict__ Wo, const float* __restrict__ bo,
    const float* __restrict__ bcoords, const float* __restrict__ W1,
    float* __restrict__ out)
{
    __shared__ float vs[TT*33];
    __shared__ float lg[HH*TT];
    __shared__ float Wos[AO*AO];
    __shared__ float Wks[4*AO], Wqs[4*AO], Wvs[2*AO];
    __shared__ float bks[AO], bqs[AO], bvs[AO], bos[AO];
    __shared__ float qs[AO], part[8*AO], attns[AO];

    int tid = threadIdx.x;
    int bid = blockIdx.x;

    if (bid < BB*NBB) {
        if (tid < LAT) {
            const float* bc = bcoords + bid * 4;
            g_bterm[bid*LAT + tid] = bc[0]*W1[4*LAT+tid] + bc[1]*W1[5*LAT+tid]
                                   + bc[2]*W1[6*LAT+tid] + bc[3]*W1[7*LAT+tid];
        }
    }

    if (tid < 128)      { Wks[tid] = Wk[tid]; Wqs[tid] = Wq[tid]; }
    else if (tid < 192) { Wvs[tid-128] = Wv[tid-128]; }
    else if (tid < 224) { int j = tid-192; bks[j] = bk[j]; bqs[j] = bq[j]; }
    else                { int j = tid-224; bvs[j] = bv[j]; bos[j] = bo[j]; }
    for (int i = tid; i < AO*AO; i += 256) Wos[i] = Wo[i];

    int b; float c0, c1, c2, c3; float* outp;
    if (bid < BB*PP) {
        b = bid / PP; int p = bid % PP;
        const float* ph = phase + (b*PP+p)*4;
        c0 = ph[0]; c1 = ph[1]; c2 = ph[2]; c3 = ph[3];
        outp = g_att_main + (b*PP+p)*AO;
    } else {
        int idx = bid - BB*PP;
        b = idx / (PP*VV); int pv = idx % (PP*VV);
        int p = pv / VV, v = pv % VV;
        const float* ph = phase + (b*PP+p)*4;
        const float* vc = vel_coords + (b*VV+v)*2;
        c0 = ph[0]; c1 = ph[1]; c2 = vc[0]; c3 = vc[1];
        outp = g_att_self + ((b*PP+p)*VV+v)*AO;
    }
    __syncthreads();

    if (tid < AO)
        qs[tid] = c0*Wqs[tid] + c1*Wqs[AO+tid] + c2*Wqs[2*AO+tid] + c3*Wqs[3*AO+tid] + bqs[tid];

    int t = tid;
    const float* pc = pos_coords + (b*TT+t)*2;
    float r0 = pc[0] - c0, r1 = pc[1] - c1;
    bool valid = (r0*c2 + r1*c3) <= 0.0f;
    const float* sg = sigma + (b*TT+t)*2;
    float s0 = sg[0], s1 = sg[1];
    float kv[AO];
#pragma unroll
    for (int j = 0; j < AO; j++) {
        kv[j] = r0*Wks[j] + r1*Wks[AO+j] + c2*Wks[2*AO+j] + c3*Wks[3*AO+j] + bks[j];
        vs[t*33+j] = s0*Wvs[j] + s1*Wvs[AO+j] + bvs[j];
    }
    __syncthreads();
#pragma unroll
    for (int h = 0; h < HH; h++) {
        float l = 0.f;
#pragma unroll
        for (int d = 0; d < 8; d++) l += qs[h*8+d] * kv[h*8+d];
        lg[h*TT+t] = valid ? l * 0.3535533905932738f : -1e30f;
    }
    __syncthreads();

    int warp = tid >> 5, lane = tid & 31;
    if (warp < HH) {
        int h = warp;
        float mx = -1e38f;
#pragma unroll
        for (int i = 0; i < 8; i++) mx = fmaxf(mx, lg[h*TT+lane+32*i]);
#pragma unroll
        for (int o = 16; o; o >>= 1) mx = fmaxf(mx, __shfl_xor_sync(0xffffffffu, mx, o));
        float e[8]; float sm = 0.f;
#pragma unroll
        for (int i = 0; i < 8; i++) { e[i] = __expf(lg[h*TT+lane+32*i] - mx); sm += e[i]; }
#pragma unroll
        for (int o = 16; o; o >>= 1) sm += __shfl_xor_sync(0xffffffffu, sm, o);
        float inv = __fdividef(1.0f, sm);
#pragma unroll
        for (int i = 0; i < 8; i++) lg[h*TT+lane+32*i] = e[i] * inv;
    }
    __syncthreads();

    {
        int j = tid & 31, ch = tid >> 5, h = j >> 3;
        float s = 0.f; int t0 = ch * 32;
#pragma unroll
        for (int k = 0; k < 32; k++) s += lg[h*TT+t0+k] * vs[(t0+k)*33+j];
        part[ch*AO+j] = s;
    }
    __syncthreads();
    if (tid < AO) {
        float s = 0.f;
#pragma unroll
        for (int ch = 0; ch < 8; ch++) s += part[ch*AO+tid];
        attns[tid] = s;
    }
    __syncthreads();
    if (tid < AO) {
        float a = bos[tid];
#pragma unroll
        for (int j = 0; j < AO; j++) a += attns[j] * Wos[j*AO+tid];
        outp[tid] = __expf(-a);
    }
}

// ---------------- fused kernel helpers ---------------------------------------
// single-tile 64x64 GEMM row slice, raw output
__device__ __forceinline__ void gemm_row_o(const float* __restrict__ src,
                                           const float* __restrict__ W,
                                           const float* __restrict__ bias,
                                           int r, int dg, float o[8])
{
    const ulonglong2* bp = (const ulonglong2*)(bias + dg);
    ulonglong2 b01 = bp[0], b23 = bp[1];
    ull a0 = b01.x, a1 = b01.y, a2 = b23.x, a3 = b23.y;
    const float* inrow = src + r*RS;
#pragma unroll 4
    for (int c = 0; c < LAT; c += 4) {
        float4 x = *(const float4*)(inrow + c);
#pragma unroll
        for (int cc = 0; cc < 4; cc++) {
            float xv = (cc==0) ? x.x : (cc==1) ? x.y : (cc==2) ? x.z : x.w;
            ull x2 = packdup(xv);
            const ulonglong2* w = (const ulonglong2*)(W + (c+cc)*LAT + dg);
            ulonglong2 w01 = w[0], w23 = w[1];
            fma2(a0, x2, w01.x); fma2(a1, x2, w01.y);
            fma2(a2, x2, w23.x); fma2(a3, x2, w23.y);
        }
    }
    float2 f0 = unpk(a0), f1 = unpk(a1), f2 = unpk(a2), f3 = unpk(a3);
    o[0]=f0.x; o[1]=f0.y; o[2]=f1.x; o[3]=f1.y;
    o[4]=f2.x; o[5]=f2.y; o[6]=f3.x; o[7]=f3.y;
}

template<bool ADD>
__device__ __forceinline__ void gemm1(const float* __restrict__ src, float* __restrict__ dst,
                                      const float* __restrict__ W, const float* __restrict__ bias,
                                      int r, int dg)
{
    float o[8]; gemm_row_o(src, W, bias, r, dg, o);
    float* d = dst + r*RS + dg;
#pragma unroll
    for (int i = 0; i < 8; i++) {
        if (ADD) d[i] += tanh_fast(o[i]); else d[i] = tanh_fast(o[i]);
    }
}

// 4-tile n-batched GEMM: W loads amortized over 4 tiles
template<bool ADD>
__device__ __forceinline__ void gemm4(const float* __restrict__ src, float* __restrict__ dst,
                                      const float* __restrict__ W, const float* __restrict__ bias,
                                      int r, int dg)
{
    ull acc[4][4];
    const ulonglong2* bp = (const ulonglong2*)(bias + dg);
    ulonglong2 b01 = bp[0], b23 = bp[1];
#pragma unroll
    for (int t = 0; t < 4; t++) { acc[t][0]=b01.x; acc[t][1]=b01.y; acc[t][2]=b23.x; acc[t][3]=b23.y; }
    const float* row = src + r*RS;
#pragma unroll 2
    for (int c4 = 0; c4 < 16; c4++) {
        float4 x0 = *(const float4*)(row + 0*TS + c4*4);
        float4 x1 = *(const float4*)(row + 1*TS + c4*4);
        float4 x2 = *(const float4*)(row + 2*TS + c4*4);
        float4 x3 = *(const float4*)(row + 3*TS + c4*4);
#pragma unroll
        for (int cc = 0; cc < 4; cc++) {
            const ulonglong2* w = (const ulonglong2*)(W + (c4*4+cc)*LAT + dg);
            ulonglong2 w01 = w[0], w23 = w[1];
            float v0 = (cc==0)?x0.x:(cc==1)?x0.y:(cc==2)?x0.z:x0.w;
            float v1 = (cc==0)?x1.x:(cc==1)?x1.y:(cc==2)?x1.z:x1.w;
            float v2 = (cc==0)?x2.x:(cc==1)?x2.y:(cc==2)?x2.z:x2.w;
            float v3 = (cc==0)?x3.x:(cc==1)?x3.y:(cc==2)?x3.z:x3.w;
            ull p0 = packdup(v0), p1 = packdup(v1), p2 = packdup(v2), p3 = packdup(v3);
            fma2(acc[0][0], p0, w01.x); fma2(acc[0][1], p0, w01.y);
            fma2(acc[0][2], p0, w23.x); fma2(acc[0][3], p0, w23.y);
            fma2(acc[1][0], p1, w01.x); fma2(acc[1][1], p1, w01.y);
            fma2(acc[1][2], p1, w23.x); fma2(acc[1][3], p1, w23.y);
            fma2(acc[2][0], p2, w01.x); fma2(acc[2][1], p2, w01.y);
            fma2(acc[2][2], p2, w23.x); fma2(acc[2][3], p2, w23.y);
            fma2(acc[3][0], p3, w01.x); fma2(acc[3][1], p3, w01.y);
            fma2(acc[3][2], p3, w23.x); fma2(acc[3][3], p3, w23.y);
        }
    }
#pragma unroll
    for (int t = 0; t < 4; t++) {
        float* o = dst + t*TS + r*RS + dg;
#pragma unroll
        for (int j = 0; j < 4; j++) {
            float2 f = unpk(acc[t][j]);
            if (ADD) { o[2*j] += tanh_fast(f.x); o[2*j+1] += tanh_fast(f.y); }
            else     { o[2*j]  = tanh_fast(f.x); o[2*j+1]  = tanh_fast(f.y); }
        }
    }
}

// single-tile mix, raw output
__device__ __forceinline__ void mix_row(const float* __restrict__ A,
                                        const float* __restrict__ sk,
                                        int dg, float o[8])
{
    ull a0=0, a1=0, a2=0, a3=0;
#pragma unroll 4
    for (int c = 0; c < VV; c++) {
        ull x2 = packdup(sk[c]);
        const ulonglong2* a = (const ulonglong2*)(A + c*RS + dg);
        ulonglong2 a01 = a[0], a23 = a[1];
        fma2(a0, x2, a01.x); fma2(a1, x2, a01.y);
        fma2(a2, x2, a23.x); fma2(a3, x2, a23.y);
    }
    float2 f0 = unpk(a0), f1 = unpk(a1), f2 = unpk(a2), f3 = unpk(a3);
    o[0]=f0.x; o[1]=f0.y; o[2]=f1.x; o[3]=f1.y;
    o[4]=f2.x; o[5]=f2.y; o[6]=f3.x; o[7]=f3.y;
}

// 4-tile mix (sk broadcast shared across tiles)
__device__ __forceinline__ void mix4(const float* __restrict__ src, float* __restrict__ dst,
                                     const float* __restrict__ sk, int r, int dg)
{
    ull acc[4][4];
#pragma unroll
    for (int t = 0; t < 4; t++) { acc[t][0]=0; acc[t][1]=0; acc[t][2]=0; acc[t][3]=0; }
#pragma unroll 2
    for (int c = 0; c < VV; c++) {
        ull s2 = packdup(sk[c]);
#pragma unroll
        for (int t = 0; t < 4; t++) {
            const ulonglong2* a = (const ulonglong2*)(src + t*TS + c*RS + dg);
            ulonglong2 a01 = a[0], a23 = a[1];
            fma2(acc[t][0], s2, a01.x); fma2(acc[t][1], s2, a01.y);
            fma2(acc[t][2], s2, a23.x); fma2(acc[t][3], s2, a23.y);
        }
    }
#pragma unroll
    for (int t = 0; t < 4; t++) {
        float* o = dst + t*TS + r*RS + dg;
#pragma unroll
        for (int j = 0; j < 4; j++) { float2 f = unpk(acc[t][j]); o[2*j]=f.x; o[2*j+1]=f.y; }
    }
}

// smem layout (floats)
#define OFF_W1   0
#define OFF_W2   (OFF_W1 + 40*LAT)          // 2560
#define OFF_WO   (OFF_W2 + LAT*LAT)         // 6656
#define OFF_WS1  (OFF_WO + LAT*LAT)         // 10752
#define OFF_WS2  (OFF_WS1 + LAT*LAT)        // 14848
#define OFF_BV   (OFF_WS2 + LAT*LAT)        // 18944 (6x64)
#define OFF_WQ   (OFF_BV + 6*LAT)           // 19328 (64)
#define OFF_SK   (OFF_WQ + NBB)             // 19392 (1092)
#define OFF_BT   (OFF_SK + 1092)            // 20484 (NBB*LAT)
#define OFF_B1   (OFF_BT + NBB*LAT)         // 24580 (TS)
#define OFF_X    (OFF_B1 + TS)              // 26824 (4*TS)
#define OFF_Y    (OFF_X + 4*TS)             // 35800 (4*TS)
#define SMEM_FLOATS (OFF_Y + 4*TS)          // 44776
#define SMEM_BYTES  (SMEM_FLOATS * 4)       // 179104

__global__ void __launch_bounds__(288, 1) fused_kernel(
    const float* __restrict__ phase, const float* __restrict__ boundary,
    const float* __restrict__ bweights, const float* __restrict__ vel_coords,
    const float* __restrict__ vweights, const float* __restrict__ scat,
    const float* __restrict__ self_scat,
    const float* __restrict__ W1, const float* __restrict__ b1,
    const float* __restrict__ W2, const float* __restrict__ b2,
    const float* __restrict__ Wout, const float* __restrict__ bout,
    const float* __restrict__ Ws1, const float* __restrict__ bs1,
    const float* __restrict__ Ws2, const float* __restrict__ bs2,
    const float* __restrict__ Wp, float* __restrict__ out)
{
    extern __shared__ float sh[];
    float* W1s  = sh + OFF_W1;
    float* W2s  = sh + OFF_W2;
    float* Wos  = sh + OFF_WO;
    float* Ws1s = sh + OFF_WS1;
    float* Ws2s = sh + OFF_WS2;
    float* b1s  = sh + OFF_BV;
    float* b2s  = b1s + LAT;
    float* bouts= b1s + 2*LAT;
    float* bs1s = b1s + 3*LAT;
    float* bs2s = b1s + 4*LAT;
    float* Wps  = b1s + 5*LAT;
    float* wqS  = sh + OFF_WQ;
    float* SKs  = sh + OFF_SK;
    float* btS  = sh + OFF_BT;
    float* base1= sh + OFF_B1;
    float* XT   = sh + OFF_X;
    float* YT   = sh + OFF_Y;

    int tid = threadIdx.x;
    int bp = blockIdx.x;              // one block per (b,p)
    int b = bp / PP, p = bp % PP;

    // phase 1: stage all weights / biases / kernels / bterm / wq
    for (int i = tid; i < 40*LAT; i += 288) W1s[i] = W1[i];
    for (int i = tid; i < LAT*LAT; i += 288) {
        W2s[i] = W2[i]; Wos[i] = Wout[i]; Ws1s[i] = Ws1[i]; Ws2s[i] = Ws2[i];
    }
    if (tid < LAT) {
        b1s[tid] = b1[tid]; b2s[tid] = b2[tid]; bouts[tid] = bout[tid];
        bs1s[tid] = bs1[tid]; bs2s[tid] = bs2[tid]; Wps[tid] = Wp[tid];
    }
    if (tid < NBB)
        wqS[tid] = boundary[b*NBB+tid] * bweights[b*NBB+tid];
    for (int i = tid; i < NBB*LAT; i += 288)
        btS[i] = g_bterm[b*NBB*LAT + i];
    for (int i = tid; i < ROWS*VV; i += 288) {
        int rr = i >> 5, v = i & 31;
        float w = vweights[b*VV+v];
        SKs[rr*33+v] = (rr < 32) ? (1.0f - self_scat[(b*VV+rr)*VV+v]) * w
                                 : (1.0f - scat[(b*PP+p)*VV+v]) * w;
    }
    __syncthreads();

    // phase 2: base1 (layer-1 preactivation minus boundary term)
    const float* ph = phase + (b*PP+p)*4;
    float p0 = ph[0], p1 = ph[1], p2 = ph[2], p3 = ph[3];
    for (int i = tid; i < ROWS*LAT; i += 288) {
        int rr = i >> 6, d = i & 63;
        float cc2, cc3; const float* att;
        if (rr < 32) {
            cc2 = vel_coords[(b*VV+rr)*2]; cc3 = vel_coords[(b*VV+rr)*2+1];
            att = g_att_self + ((b*PP+p)*VV+rr)*AO;
        } else {
            cc2 = p2; cc3 = p3;
            att = g_att_main + (b*PP+p)*AO;
        }
        float s = b1s[d] + p0*W1s[d] + p1*W1s[LAT+d] + cc2*W1s[2*LAT+d] + cc3*W1s[3*LAT+d];
#pragma unroll 8
        for (int j = 0; j < AO; j++) s += att[j] * W1s[(8+j)*LAT+d];
        base1[rr*RS+d] = s;
    }
    __syncthreads();

    // thread mapping
    int r = 0, dg = 0, lane8 = 0, t8 = 0, dg8 = 0;
    if (tid < 256) { r = tid >> 3; dg = (tid & 7) << 3; }
    else { lane8 = tid - 256; t8 = lane8 >> 3; dg8 = (lane8 & 7) << 3; }

    // preload this thread's base1 slice into registers (constant across n)
    float baseR[8];
    {
        const float* bsrc = base1 + ((tid < 256) ? (r*RS + dg) : (32*RS + dg8));
        float4 a = *(const float4*)bsrc, c = *(const float4*)(bsrc + 4);
        baseR[0]=a.x; baseR[1]=a.y; baseR[2]=a.z; baseR[3]=a.w;
        baseR[4]=c.x; baseR[5]=c.y; baseR[6]=c.z; baseR[7]=c.w;
    }

    float accOut = 0.f;
    for (int n4 = 0; n4 < NBB/4; ++n4) {
        __syncthreads();                 // X/Y tiles free (incl. warp-8 trailing reads)
        // ---- layer 1 + boundary term -> X tiles ----
        if (tid < 256) {
#pragma unroll
            for (int t = 0; t < 4; t++) {
                const float* bt = btS + (n4*4+t)*LAT + dg;
                float4 b0 = *(const float4*)bt, b1v = *(const float4*)(bt+4);
                float* xo = XT + t*TS + r*RS + dg;
                xo[0]=tanh_fast(baseR[0]+b0.x);  xo[1]=tanh_fast(baseR[1]+b0.y);
                xo[2]=tanh_fast(baseR[2]+b0.z);  xo[3]=tanh_fast(baseR[3]+b0.w);
                xo[4]=tanh_fast(baseR[4]+b1v.x); xo[5]=tanh_fast(baseR[5]+b1v.y);
                xo[6]=tanh_fast(baseR[6]+b1v.z); xo[7]=tanh_fast(baseR[7]+b1v.w);
            }
            __syncwarp();
            gemm4<false>(XT, YT, W2s, b2s, r, dg);       // layer 2
            __syncwarp();
            gemm4<false>(YT, XT, Wos, bouts, r, dg);     // layer 3
        } else {
            const float* bt = btS + (n4*4+t8)*LAT + dg8;
            float4 b0 = *(const float4*)bt, b1v = *(const float4*)(bt+4);
            float* xo = XT + t8*TS + 32*RS + dg8;
            xo[0]=tanh_fast(baseR[0]+b0.x);  xo[1]=tanh_fast(baseR[1]+b0.y);
            xo[2]=tanh_fast(baseR[2]+b0.z);  xo[3]=tanh_fast(baseR[3]+b0.w);
            xo[4]=tanh_fast(baseR[4]+b1v.x); xo[5]=tanh_fast(baseR[5]+b1v.y);
            xo[6]=tanh_fast(baseR[6]+b1v.z); xo[7]=tanh_fast(baseR[7]+b1v.w);
            __syncwarp();
            gemm1<false>(XT + t8*TS, YT + t8*TS, W2s, b2s, 32, dg8);
            __syncwarp();
            gemm1<false>(YT + t8*TS, XT + t8*TS, Wos, bouts, 32, dg8);
        }
        __syncthreads();                 // full tiles visible for mix 1
        // ---- mix 1 (reads X rows 0..31) -> Y ----
        if (tid < 256) {
            mix4(XT, YT, SKs + r*33, r, dg);
        } else {
            float m[8]; mix_row(XT + t8*TS, SKs + 32*33, dg8, m);
            float* yo = YT + t8*TS + 32*RS + dg8;
#pragma unroll
            for (int i = 0; i < 8; i++) yo[i] = m[i];
        }
        __syncthreads();                 // all mix1 reads done before Ws1 writes X
        // ---- Ws1 update (row-local) ----
        if (tid < 256) {
            gemm4<true>(YT, XT, Ws1s, bs1s, r, dg);
        } else {
            gemm1<true>(YT + t8*TS, XT + t8*TS, Ws1s, bs1s, 32, dg8);
        }
        __syncthreads();                 // post-Ws1 tiles visible for warp-8 mix 2
        // ---- warp-8 tail: mix2 + Ws2 + green for 4 tiles in parallel ----
        if (tid >= 256) {
            float m[8]; mix_row(XT + t8*TS, SKs + 32*33, dg8, m);
            float* yo = YT + t8*TS + 32*RS + dg8;
#pragma unroll
            for (int i = 0; i < 8; i++) yo[i] = m[i];
            __syncwarp();
            float o[8]; gemm_row_o(YT + t8*TS, Ws2s, bs2s, 32, dg8, o);
            const float* xr = XT + t8*TS + 32*RS + dg8;
            float s = 0.f;
#pragma unroll
            for (int i = 0; i < 8; i++)
                s += (xr[i] + tanh_fast(o[i])) * Wps[dg8+i];
            s += __shfl_xor_sync(0xffffffffu, s, 1);
            s += __shfl_xor_sync(0xffffffffu, s, 2);
            s += __shfl_xor_sync(0xffffffffu, s, 4);
            if ((lane8 & 7) == 0)
                accOut += __expf(s) * wqS[n4*4 + t8];
        }
    }
    if (tid >= 256) {
        accOut += __shfl_xor_sync(0xffffffffu, accOut, 8);
        accOut += __shfl_xor_sync(0xffffffffu, accOut, 16);
        if (lane8 == 0) out[bp] = accOut;
    }
}

extern "C" void kernel_launch(void* const* d_in, const int* in_sizes, int n_in,
                              void* d_out, int out_size)
{
    const float* phase   = (const float*)d_in[0];
    const float* bcoords = (const float*)d_in[1];
    const float* boundary= (const float*)d_in[2];
    const float* bweights= (const float*)d_in[3];
    const float* poscrd  = (const float*)d_in[4];
    const float* sigma   = (const float*)d_in[5];
    const float* velcrd  = (const float*)d_in[6];
    const float* vweights= (const float*)d_in[7];
    const float* scat    = (const float*)d_in[8];
    const float* sscat   = (const float*)d_in[9];
    const float* Wq = (const float*)d_in[10]; const float* bq = (const float*)d_in[11];
    const float* Wk = (const float*)d_in[12]; const float* bk = (const float*)d_in[13];
    const float* Wv = (const float*)d_in[14]; const float* bv = (const float*)d_in[15];
    const float* Wo = (const float*)d_in[16]; const float* bo = (const float*)d_in[17];
    const float* W1 = (const float*)d_in[18]; const float* b1 = (const float*)d_in[19];
    const float* W2 = (const float*)d_in[20]; const float* b2 = (const float*)d_in[21];
    const float* Wout = (const float*)d_in[22]; const float* bout = (const float*)d_in[23];
    const float* Ws1 = (const float*)d_in[24]; const float* bs1 = (const float*)d_in[25];
    const float* Ws2 = (const float*)d_in[26]; const float* bs2 = (const float*)d_in[27];
    const float* Wp = (const float*)d_in[28];
    float* out = (float*)d_out;

    cudaFuncSetAttribute(fused_kernel,
                         cudaFuncAttributeMaxDynamicSharedMemorySize, SMEM_BYTES);

    att_kernel<<<BB*PP + BB*PP*VV, 256>>>(phase, poscrd, sigma, velcrd,
                                          Wq, bq, Wk, bk, Wv, bv, Wo, bo,
                                          bcoords, W1, out);
    fused_kernel<<<BB*PP, 288, SMEM_BYTES>>>(
        phase, boundary, bweights, velcrd, vweights, scat, sscat,
        W1, b1, W2, b2, Wout, bout, Ws1, bs1, Ws2, bs2, Wp, out);
}

// round 9
// speedup vs baseline: 3.6175x; 1.2513x over previous
#include <cuda_runtime.h>
#include <math.h>

#define BB  2
#define PP  64
#define NBB 64
#define TT  256
#define VV  32
#define HH  4
#define AO  32
#define LAT 64
#define RS  68
#define ROWS 33
#define TS  (32*RS)     // 2176 floats per 32-row tile
#define VST 68          // act-row vector stride

typedef unsigned long long ull;

__device__ float g_att_main[BB*PP*AO];
__device__ float g_att_self[BB*PP*VV*AO];
__device__ float g_bterm[BB*NBB*LAT];

__device__ __forceinline__ float tanh_fast(float x) {
    float e = __expf(2.0f * x);
    return 1.0f - __fdividef(2.0f, e + 1.0f);
}
__device__ __forceinline__ ull packdup(float x) {
    ull r; asm("mov.b64 %0,{%1,%1};" : "=l"(r) : "f"(x)); return r;
}
__device__ __forceinline__ void fma2(ull& d, ull a, ull b) {
    asm("fma.rn.f32x2 %0,%1,%2,%0;" : "+l"(d) : "l"(a), "l"(b));
}
__device__ __forceinline__ float2 unpk(ull a) {
    float2 f; asm("mov.b64 {%0,%1},%2;" : "=f"(f.x), "=f"(f.y) : "l"(a)); return f;
}

// ---------------- attention (+ absorbed prep) --------------------------------
__global__ void __launch_bounds__(256) att_kernel(
    const float* __restrict__ phase, const float* __restrict__ pos_coords,
    const float* __restrict__ sigma, const float* __restrict__ vel_coords,
    const float* __restrict__ Wq, const float* __restrict__ bq,
    const float* __restrict__ Wk, const float* __restrict__ bk,
    const float* __restrict__ Wv, const float* __restrict__ bv,
    const float* __restrict__ Wo, const float* __restrict__ bo,
    const float* __restrict__ bcoords, const float* __restrict__ W1)
{
    __shared__ float vs[TT*33];
    __shared__ float lg[HH*TT];
    __shared__ float Wos[AO*AO];
    __shared__ float Wks[4*AO], Wqs[4*AO], Wvs[2*AO];
    __shared__ float bks[AO], bqs[AO], bvs[AO], bos[AO];
    __shared__ float qs[AO], part[8*AO], attns[AO];

    int tid = threadIdx.x;
    int bid = blockIdx.x;

    if (bid < BB*NBB && tid < LAT) {
        const float* bc = bcoords + bid * 4;
        g_bterm[bid*LAT + tid] = bc[0]*W1[4*LAT+tid] + bc[1]*W1[5*LAT+tid]
                               + bc[2]*W1[6*LAT+tid] + bc[3]*W1[7*LAT+tid];
    }

    if (tid < 128)      { Wks[tid] = Wk[tid]; Wqs[tid] = Wq[tid]; }
    else if (tid < 192) { Wvs[tid-128] = Wv[tid-128]; }
    else if (tid < 224) { int j = tid-192; bks[j] = bk[j]; bqs[j] = bq[j]; }
    else                { int j = tid-224; bvs[j] = bv[j]; bos[j] = bo[j]; }
    for (int i = tid; i < AO*AO; i += 256) Wos[i] = Wo[i];

    int b; float c0, c1, c2, c3; float* outp;
    if (bid < BB*PP) {
        b = bid / PP; int p = bid % PP;
        const float* ph = phase + (b*PP+p)*4;
        c0 = ph[0]; c1 = ph[1]; c2 = ph[2]; c3 = ph[3];
        outp = g_att_main + (b*PP+p)*AO;
    } else {
        int idx = bid - BB*PP;
        b = idx / (PP*VV); int pv = idx % (PP*VV);
        int p = pv / VV, v = pv % VV;
        const float* ph = phase + (b*PP+p)*4;
        const float* vc = vel_coords + (b*VV+v)*2;
        c0 = ph[0]; c1 = ph[1]; c2 = vc[0]; c3 = vc[1];
        outp = g_att_self + ((b*PP+p)*VV+v)*AO;
    }
    __syncthreads();

    if (tid < AO)
        qs[tid] = c0*Wqs[tid] + c1*Wqs[AO+tid] + c2*Wqs[2*AO+tid] + c3*Wqs[3*AO+tid] + bqs[tid];

    int t = tid;
    const float* pc = pos_coords + (b*TT+t)*2;
    float r0 = pc[0] - c0, r1 = pc[1] - c1;
    bool valid = (r0*c2 + r1*c3) <= 0.0f;
    const float* sg = sigma + (b*TT+t)*2;
    float s0 = sg[0], s1 = sg[1];
    float kv[AO];
#pragma unroll
    for (int j = 0; j < AO; j++) {
        kv[j] = r0*Wks[j] + r1*Wks[AO+j] + c2*Wks[2*AO+j] + c3*Wks[3*AO+j] + bks[j];
        vs[t*33+j] = s0*Wvs[j] + s1*Wvs[AO+j] + bvs[j];
    }
    __syncthreads();
#pragma unroll
    for (int h = 0; h < HH; h++) {
        float l = 0.f;
#pragma unroll
        for (int d = 0; d < 8; d++) l += qs[h*8+d] * kv[h*8+d];
        lg[h*TT+t] = valid ? l * 0.3535533905932738f : -1e30f;
    }
    __syncthreads();

    int warp = tid >> 5, lane = tid & 31;
    if (warp < HH) {
        int h = warp;
        float mx = -1e38f;
#pragma unroll
        for (int i = 0; i < 8; i++) mx = fmaxf(mx, lg[h*TT+lane+32*i]);
#pragma unroll
        for (int o = 16; o; o >>= 1) mx = fmaxf(mx, __shfl_xor_sync(0xffffffffu, mx, o));
        float e[8]; float sm = 0.f;
#pragma unroll
        for (int i = 0; i < 8; i++) { e[i] = __expf(lg[h*TT+lane+32*i] - mx); sm += e[i]; }
#pragma unroll
        for (int o = 16; o; o >>= 1) sm += __shfl_xor_sync(0xffffffffu, sm, o);
        float inv = __fdividef(1.0f, sm);
#pragma unroll
        for (int i = 0; i < 8; i++) lg[h*TT+lane+32*i] = e[i] * inv;
    }
    __syncthreads();

    {
        int j = tid & 31, ch = tid >> 5, h = j >> 3;
        float s = 0.f; int t0 = ch * 32;
#pragma unroll
        for (int k = 0; k < 32; k++) s += lg[h*TT+t0+k] * vs[(t0+k)*33+j];
        part[ch*AO+j] = s;
    }
    __syncthreads();
    if (tid < AO) {
        float s = 0.f;
#pragma unroll
        for (int ch = 0; ch < 8; ch++) s += part[ch*AO+tid];
        attns[tid] = s;
    }
    __syncthreads();
    if (tid < AO) {
        float a = bos[tid];
#pragma unroll
        for (int j = 0; j < AO; j++) a += attns[j] * Wos[j*AO+tid];
        outp[tid] = __expf(-a);
    }
}

// ---------------- fused kernel helpers ---------------------------------------
// 8-tile batched 64x64 GEMM for one row slice
template<bool ADD>
__device__ __forceinline__ void gemm8(const float* __restrict__ src, float* __restrict__ dst,
                                      const float* __restrict__ W, const float* __restrict__ bias,
                                      int r, int dg)
{
    ull acc[8][4];
    const ulonglong2* bp = (const ulonglong2*)(bias + dg);
    ulonglong2 b01 = bp[0], b23 = bp[1];
#pragma unroll
    for (int t = 0; t < 8; t++) { acc[t][0]=b01.x; acc[t][1]=b01.y; acc[t][2]=b23.x; acc[t][3]=b23.y; }
    const float* row = src + r*RS;
#pragma unroll 2
    for (int c4 = 0; c4 < 16; c4++) {
        float4 x[8];
#pragma unroll
        for (int t = 0; t < 8; t++) x[t] = *(const float4*)(row + t*TS + c4*4);
#pragma unroll
        for (int cc = 0; cc < 4; cc++) {
            const ulonglong2* w = (const ulonglong2*)(W + (c4*4+cc)*LAT + dg);
            ulonglong2 w01 = w[0], w23 = w[1];
#pragma unroll
            for (int t = 0; t < 8; t++) {
                float xv = (cc==0)?x[t].x:(cc==1)?x[t].y:(cc==2)?x[t].z:x[t].w;
                ull p = packdup(xv);
                fma2(acc[t][0], p, w01.x); fma2(acc[t][1], p, w01.y);
                fma2(acc[t][2], p, w23.x); fma2(acc[t][3], p, w23.y);
            }
        }
    }
#pragma unroll
    for (int t = 0; t < 8; t++) {
        float* o = dst + t*TS + r*RS + dg;
        float2 f0=unpk(acc[t][0]), f1=unpk(acc[t][1]), f2=unpk(acc[t][2]), f3=unpk(acc[t][3]);
        if (ADD) {
            float4 e0 = *(float4*)o, e1 = *(float4*)(o+4);
            e0.x += tanh_fast(f0.x); e0.y += tanh_fast(f0.y); e0.z += tanh_fast(f1.x); e0.w += tanh_fast(f1.y);
            e1.x += tanh_fast(f2.x); e1.y += tanh_fast(f2.y); e1.z += tanh_fast(f3.x); e1.w += tanh_fast(f3.y);
            *(float4*)o = e0; *(float4*)(o+4) = e1;
        } else {
            float4 e0 = make_float4(tanh_fast(f0.x),tanh_fast(f0.y),tanh_fast(f1.x),tanh_fast(f1.y));
            float4 e1 = make_float4(tanh_fast(f2.x),tanh_fast(f2.y),tanh_fast(f3.x),tanh_fast(f3.y));
            *(float4*)o = e0; *(float4*)(o+4) = e1;
        }
    }
}

// 8-tile mix (sk broadcast shared across tiles), raw output
__device__ __forceinline__ void mix8(const float* __restrict__ src, float* __restrict__ dst,
                                     const float* __restrict__ sk, int r, int dg)
{
    ull acc[8][4];
#pragma unroll
    for (int t = 0; t < 8; t++) { acc[t][0]=0; acc[t][1]=0; acc[t][2]=0; acc[t][3]=0; }
#pragma unroll 2
    for (int c = 0; c < VV; c++) {
        ull s2 = packdup(sk[c]);
#pragma unroll
        for (int t = 0; t < 8; t++) {
            const ulonglong2* a = (const ulonglong2*)(src + t*TS + c*RS + dg);
            ulonglong2 a01 = a[0], a23 = a[1];
            fma2(acc[t][0], s2, a01.x); fma2(acc[t][1], s2, a01.y);
            fma2(acc[t][2], s2, a23.x); fma2(acc[t][3], s2, a23.y);
        }
    }
#pragma unroll
    for (int t = 0; t < 8; t++) {
        float* o = dst + t*TS + r*RS + dg;
        float2 f0=unpk(acc[t][0]), f1=unpk(acc[t][1]), f2=unpk(acc[t][2]), f3=unpk(acc[t][3]);
        *(float4*)o     = make_float4(f0.x,f0.y,f1.x,f1.y);
        *(float4*)(o+4) = make_float4(f2.x,f2.y,f3.x,f3.y);
    }
}

// warp-8: 2 act-row vectors GEMM (tiles ta, ta+1 stored as 68-float vectors)
template<bool ADD>
__device__ __forceinline__ void gemm2v(const float* __restrict__ src, float* __restrict__ dst,
                                       const float* __restrict__ W, const float* __restrict__ bias,
                                       int ta, int dg)
{
    ull acc[2][4];
    const ulonglong2* bp = (const ulonglong2*)(bias + dg);
    ulonglong2 b01 = bp[0], b23 = bp[1];
#pragma unroll
    for (int k = 0; k < 2; k++) { acc[k][0]=b01.x; acc[k][1]=b01.y; acc[k][2]=b23.x; acc[k][3]=b23.y; }
#pragma unroll 4
    for (int c4 = 0; c4 < 16; c4++) {
        float4 xa = *(const float4*)(src + ta*VST + c4*4);
        float4 xb = *(const float4*)(src + (ta+1)*VST + c4*4);
#pragma unroll
        for (int cc = 0; cc < 4; cc++) {
            const ulonglong2* w = (const ulonglong2*)(W + (c4*4+cc)*LAT + dg);
            ulonglong2 w01 = w[0], w23 = w[1];
            float va = (cc==0)?xa.x:(cc==1)?xa.y:(cc==2)?xa.z:xa.w;
            float vb = (cc==0)?xb.x:(cc==1)?xb.y:(cc==2)?xb.z:xb.w;
            ull pa = packdup(va), pb = packdup(vb);
            fma2(acc[0][0], pa, w01.x); fma2(acc[0][1], pa, w01.y);
            fma2(acc[0][2], pa, w23.x); fma2(acc[0][3], pa, w23.y);
            fma2(acc[1][0], pb, w01.x); fma2(acc[1][1], pb, w01.y);
            fma2(acc[1][2], pb, w23.x); fma2(acc[1][3], pb, w23.y);
        }
    }
#pragma unroll
    for (int k = 0; k < 2; k++) {
        float* o = dst + (ta+k)*VST + dg;
        float2 f0=unpk(acc[k][0]), f1=unpk(acc[k][1]), f2=unpk(acc[k][2]), f3=unpk(acc[k][3]);
        if (ADD) {
            float4 e0 = *(float4*)o, e1 = *(float4*)(o+4);
            e0.x += tanh_fast(f0.x); e0.y += tanh_fast(f0.y); e0.z += tanh_fast(f1.x); e0.w += tanh_fast(f1.y);
            e1.x += tanh_fast(f2.x); e1.y += tanh_fast(f2.y); e1.z += tanh_fast(f3.x); e1.w += tanh_fast(f3.y);
            *(float4*)o = e0; *(float4*)(o+4) = e1;
        } else {
            *(float4*)o     = make_float4(tanh_fast(f0.x),tanh_fast(f0.y),tanh_fast(f1.x),tanh_fast(f1.y));
            *(float4*)(o+4) = make_float4(tanh_fast(f2.x),tanh_fast(f2.y),tanh_fast(f3.x),tanh_fast(f3.y));
        }
    }
}

// warp-8: act mix for 2 tiles (SK row 32 @ XT tile rows) -> vectors
__device__ __forceinline__ void mix2v(const float* __restrict__ XTb, float* __restrict__ dst,
                                      const float* __restrict__ sk, int ta, int dg)
{
    ull acc[2][4];
#pragma unroll
    for (int k = 0; k < 2; k++) { acc[k][0]=0; acc[k][1]=0; acc[k][2]=0; acc[k][3]=0; }
#pragma unroll 4
    for (int c = 0; c < VV; c++) {
        ull s2 = packdup(sk[c]);
#pragma unroll
        for (int k = 0; k < 2; k++) {
            const ulonglong2* a = (const ulonglong2*)(XTb + (ta+k)*TS + c*RS + dg);
            ulonglong2 a01 = a[0], a23 = a[1];
            fma2(acc[k][0], s2, a01.x); fma2(acc[k][1], s2, a01.y);
            fma2(acc[k][2], s2, a23.x); fma2(acc[k][3], s2, a23.y);
        }
    }
#pragma unroll
    for (int k = 0; k < 2; k++) {
        float* o = dst + (ta+k)*VST + dg;
        float2 f0=unpk(acc[k][0]), f1=unpk(acc[k][1]), f2=unpk(acc[k][2]), f3=unpk(acc[k][3]);
        *(float4*)o     = make_float4(f0.x,f0.y,f1.x,f1.y);
        *(float4*)(o+4) = make_float4(f2.x,f2.y,f3.x,f3.y);
    }
}

// single-vector GEMM raw (for Ws2)
__device__ __forceinline__ void gemmv_o(const float* __restrict__ v,
                                        const float* __restrict__ W,
                                        const float* __restrict__ bias,
                                        int dg, float o[8])
{
    const ulonglong2* bp = (const ulonglong2*)(bias + dg);
    ulonglong2 b01 = bp[0], b23 = bp[1];
    ull a0 = b01.x, a1 = b01.y, a2 = b23.x, a3 = b23.y;
#pragma unroll 4
    for (int c4 = 0; c4 < 16; c4++) {
        float4 x = *(const float4*)(v + c4*4);
#pragma unroll
        for (int cc = 0; cc < 4; cc++) {
            float xv = (cc==0)?x.x:(cc==1)?x.y:(cc==2)?x.z:x.w;
            ull p = packdup(xv);
            const ulonglong2* w = (const ulonglong2*)(W + (c4*4+cc)*LAT + dg);
            ulonglong2 w01 = w[0], w23 = w[1];
            fma2(a0, p, w01.x); fma2(a1, p, w01.y);
            fma2(a2, p, w23.x); fma2(a3, p, w23.y);
        }
    }
    float2 f0=unpk(a0), f1=unpk(a1), f2=unpk(a2), f3=unpk(a3);
    o[0]=f0.x; o[1]=f0.y; o[2]=f1.x; o[3]=f1.y;
    o[4]=f2.x; o[5]=f2.y; o[6]=f3.x; o[7]=f3.y;
}

// smem layout (floats)
#define OFF_W2   0
#define OFF_WO   (OFF_W2 + LAT*LAT)        // 4096
#define OFF_WS1  (OFF_WO + LAT*LAT)        // 8192
#define OFF_WS2  (OFF_WS1 + LAT*LAT)       // 12288
#define OFF_BV   (OFF_WS2 + LAT*LAT)       // 16384 (6*64)
#define OFF_WQ   (OFF_BV + 6*LAT)          // 16768 (64)
#define OFF_SK   (OFF_WQ + NBB)            // 16832 (1092)
#define OFF_XA   (OFF_SK + 1092)           // 17924 (8*68)
#define OFF_YA   (OFF_XA + 8*VST)          // 18468 (8*68)
#define OFF_X    (OFF_YA + 8*VST)          // 19012 (8*TS)
#define OFF_Y    (OFF_X + 8*TS)            // 36420 (8*TS)
#define SMEM_FLOATS (OFF_Y + 8*TS)         // 53828
#define SMEM_BYTES  (SMEM_FLOATS * 4)      // 215312

__global__ void __launch_bounds__(288, 1) fused_kernel(
    const float* __restrict__ phase, const float* __restrict__ boundary,
    const float* __restrict__ bweights, const float* __restrict__ vel_coords,
    const float* __restrict__ vweights, const float* __restrict__ scat,
    const float* __restrict__ self_scat,
    const float* __restrict__ W1, const float* __restrict__ b1,
    const float* __restrict__ W2, const float* __restrict__ b2,
    const float* __restrict__ Wout, const float* __restrict__ bout,
    const float* __restrict__ Ws1, const float* __restrict__ bs1,
    const float* __restrict__ Ws2, const float* __restrict__ bs2,
    const float* __restrict__ Wp, float* __restrict__ out)
{
    extern __shared__ float sh[];
    float* W2s  = sh + OFF_W2;
    float* Wos  = sh + OFF_WO;
    float* Ws1s = sh + OFF_WS1;
    float* Ws2s = sh + OFF_WS2;
    float* b1s  = sh + OFF_BV;
    float* b2s  = b1s + LAT;
    float* bouts= b1s + 2*LAT;
    float* bs1s = b1s + 3*LAT;
    float* bs2s = b1s + 4*LAT;
    float* Wps  = b1s + 5*LAT;
    float* wqS  = sh + OFF_WQ;
    float* SKs  = sh + OFF_SK;
    float* xA   = sh + OFF_XA;
    float* yA   = sh + OFF_YA;
    float* XT   = sh + OFF_X;
    float* YT   = sh + OFF_Y;
    float* W1s  = XT;                 // overlay: dead before loop
    float* base1= YT;                 // overlay: dead before loop

    int tid = threadIdx.x;
    int bp = blockIdx.x;
    int b = bp / PP, p = bp % PP;

    // prologue: stage weights etc.
    for (int i = tid; i < 40*LAT; i += 288) W1s[i] = W1[i];
    for (int i = tid; i < LAT*LAT; i += 288) {
        W2s[i] = W2[i]; Wos[i] = Wout[i]; Ws1s[i] = Ws1[i]; Ws2s[i] = Ws2[i];
    }
    if (tid < LAT) {
        b1s[tid] = b1[tid]; b2s[tid] = b2[tid]; bouts[tid] = bout[tid];
        bs1s[tid] = bs1[tid]; bs2s[tid] = bs2[tid]; Wps[tid] = Wp[tid];
    }
    if (tid < NBB)
        wqS[tid] = boundary[b*NBB+tid] * bweights[b*NBB+tid];
    for (int i = tid; i < ROWS*VV; i += 288) {
        int rr = i >> 5, v = i & 31;
        float w = vweights[b*VV+v];
        SKs[rr*33+v] = (rr < 32) ? (1.0f - self_scat[(b*VV+rr)*VV+v]) * w
                                 : (1.0f - scat[(b*PP+p)*VV+v]) * w;
    }
    __syncthreads();

    const float* ph = phase + (b*PP+p)*4;
    float p0 = ph[0], p1 = ph[1], p2 = ph[2], p3 = ph[3];
    for (int i = tid; i < ROWS*LAT; i += 288) {
        int rr = i >> 6, d = i & 63;
        float cc2, cc3; const float* att;
        if (rr < 32) {
            cc2 = vel_coords[(b*VV+rr)*2]; cc3 = vel_coords[(b*VV+rr)*2+1];
            att = g_att_self + ((b*PP+p)*VV+rr)*AO;
        } else {
            cc2 = p2; cc3 = p3;
            att = g_att_main + (b*PP+p)*AO;
        }
        float s = b1s[d] + p0*W1s[d] + p1*W1s[LAT+d] + cc2*W1s[2*LAT+d] + cc3*W1s[3*LAT+d];
#pragma unroll 8
        for (int j = 0; j < AO; j++) s += att[j] * W1s[(8+j)*LAT+d];
        base1[rr*RS+d] = s;
    }
    __syncthreads();

    // thread mapping
    int r = 0, dg = 0, lane8 = 0, p8 = 0, dg8 = 0;
    if (tid < 256) { r = tid >> 3; dg = (tid & 7) << 3; }
    else { lane8 = tid - 256; p8 = lane8 >> 3; dg8 = (lane8 & 7) << 3; }

    float baseR[8];
    {
        const float* bsrc = base1 + ((tid < 256) ? (r*RS + dg) : (32*RS + dg8));
        float4 a = *(const float4*)bsrc, c = *(const float4*)(bsrc + 4);
        baseR[0]=a.x; baseR[1]=a.y; baseR[2]=a.z; baseR[3]=a.w;
        baseR[4]=c.x; baseR[5]=c.y; baseR[6]=c.z; baseR[7]=c.w;
    }

    const float* btG = g_bterm + b*NBB*LAT;
    float accOut = 0.f;
    for (int it = 0; it < NBB/8; ++it) {
        __syncthreads();                 // X/Y/xA/yA free (incl. warp-8 trailing reads of XT)
        int nb0 = it*8;
        if (tid < 256) {
            // layer 1 + boundary term -> XT
#pragma unroll
            for (int t = 0; t < 8; t++) {
                const float* bt = btG + (nb0+t)*LAT + dg;
                float4 b0 = *(const float4*)bt, b1v = *(const float4*)(bt+4);
                float* xo = XT + t*TS + r*RS + dg;
                *(float4*)xo = make_float4(tanh_fast(baseR[0]+b0.x), tanh_fast(baseR[1]+b0.y),
                                           tanh_fast(baseR[2]+b0.z), tanh_fast(baseR[3]+b0.w));
                *(float4*)(xo+4) = make_float4(tanh_fast(baseR[4]+b1v.x), tanh_fast(baseR[5]+b1v.y),
                                               tanh_fast(baseR[6]+b1v.z), tanh_fast(baseR[7]+b1v.w));
            }
            __syncwarp();
            gemm8<false>(XT, YT, W2s, b2s, r, dg);     // layer 2
            __syncwarp();
            gemm8<false>(YT, XT, Wos, bouts, r, dg);   // layer 3
        } else {
            int ta = 2*p8;
#pragma unroll
            for (int k = 0; k < 2; k++) {
                const float* bt = btG + (nb0+ta+k)*LAT + dg8;
                float4 b0 = *(const float4*)bt, b1v = *(const float4*)(bt+4);
                float* xo = xA + (ta+k)*VST + dg8;
                *(float4*)xo = make_float4(tanh_fast(baseR[0]+b0.x), tanh_fast(baseR[1]+b0.y),
                                           tanh_fast(baseR[2]+b0.z), tanh_fast(baseR[3]+b0.w));
                *(float4*)(xo+4) = make_float4(tanh_fast(baseR[4]+b1v.x), tanh_fast(baseR[5]+b1v.y),
                                               tanh_fast(baseR[6]+b1v.z), tanh_fast(baseR[7]+b1v.w));
            }
            __syncwarp();
            gemm2v<false>(xA, yA, W2s, b2s, ta, dg8);
            __syncwarp();
            gemm2v<false>(yA, xA, Wos, bouts, ta, dg8);
        }
        __syncthreads();                 // full XT tiles visible for mix 1
        if (tid < 256) {
            mix8(XT, YT, SKs + r*33, r, dg);
        } else {
            mix2v(XT, yA, SKs + 32*33, 2*p8, dg8);
        }
        __syncthreads();                 // all mix1 reads done before Ws1 writes XT
        if (tid < 256) {
            gemm8<true>(YT, XT, Ws1s, bs1s, r, dg);
        } else {
            gemm2v<true>(yA, xA, Ws1s, bs1s, 2*p8, dg8);
        }
        __syncthreads();                 // post-Ws1 XT stable for warp-8 mix 2
        if (tid >= 256) {
            int ta = 2*p8;
            mix2v(XT, yA, SKs + 32*33, ta, dg8);   // mix2 -> yA
            __syncwarp();
#pragma unroll
            for (int k = 0; k < 2; k++) {
                float o[8]; gemmv_o(yA + (ta+k)*VST, Ws2s, bs2s, dg8, o);
                const float* xr = xA + (ta+k)*VST + dg8;
                float s = 0.f;
#pragma unroll
                for (int i = 0; i < 8; i++)
                    s += (xr[i] + tanh_fast(o[i])) * Wps[dg8+i];
                s += __shfl_xor_sync(0xffffffffu, s, 1);
                s += __shfl_xor_sync(0xffffffffu, s, 2);
                s += __shfl_xor_sync(0xffffffffu, s, 4);
                if ((lane8 & 7) == 0)
                    accOut += __expf(s) * wqS[nb0 + ta + k];
            }
        }
    }
    if (tid >= 256) {
        accOut += __shfl_xor_sync(0xffffffffu, accOut, 8);
        accOut += __shfl_xor_sync(0xffffffffu, accOut, 16);
        if (lane8 == 0) out[bp] = accOut;
    }
}

extern "C" void kernel_launch(void* const* d_in, const int* in_sizes, int n_in,
                              void* d_out, int out_size)
{
    const float* phase   = (const float*)d_in[0];
    const float* bcoords = (const float*)d_in[1];
    const float* boundary= (const float*)d_in[2];
    const float* bweights= (const float*)d_in[3];
    const float* poscrd  = (const float*)d_in[4];
    const float* sigma   = (const float*)d_in[5];
    const float* velcrd  = (const float*)d_in[6];
    const float* vweights= (const float*)d_in[7];
    const float* scat    = (const float*)d_in[8];
    const float* sscat   = (const float*)d_in[9];
    const float* Wq = (const float*)d_in[10]; const float* bq = (const float*)d_in[11];
    const float* Wk = (const float*)d_in[12]; const float* bk = (const float*)d_in[13];
    const float* Wv = (const float*)d_in[14]; const float* bv = (const float*)d_in[15];
    const float* Wo = (const float*)d_in[16]; const float* bo = (const float*)d_in[17];
    const float* W1 = (const float*)d_in[18]; const float* b1 = (const float*)d_in[19];
    const float* W2 = (const float*)d_in[20]; const float* b2 = (const float*)d_in[21];
    const float* Wout = (const float*)d_in[22]; const float* bout = (const float*)d_in[23];
    const float* Ws1 = (const float*)d_in[24]; const float* bs1 = (const float*)d_in[25];
    const float* Ws2 = (const float*)d_in[26]; const float* bs2 = (const float*)d_in[27];
    const float* Wp = (const float*)d_in[28];
    float* out = (float*)d_out;

    cudaFuncSetAttribute(fused_kernel,
                         cudaFuncAttributeMaxDynamicSharedMemorySize, SMEM_BYTES);

    att_kernel<<<BB*PP + BB*PP*VV, 256>>>(phase, poscrd, sigma, velcrd,
                                          Wq, bq, Wk, bk, Wv, bv, Wo, bo,
                                          bcoords, W1);
    fused_kernel<<<BB*PP, 288, SMEM_BYTES>>>(
        phase, boundary, bweights, velcrd, vweights, scat, sscat,
        W1, b1, W2, b2, Wout, bout, Ws1, bs1, Ws2, bs2, Wp, out);
}